// round 5
// baseline (speedup 1.0000x reference)
#include <cuda_runtime.h>
#include <math_constants.h>

#define NN 50000
#define NE 800000
#define HID 128

// ---------------- scratch ----------------
__device__ float g_img_f[NN * HID];
__device__ float g_txt_f[NN * HID];
__device__ float g_z[NN * HID];
__device__ float g_esrc[NN];
__device__ float g_edst[NN];
__device__ int   g_cnt[NN];
__device__ int   g_fill[NN];
__device__ int   g_row[NN + 1];
__device__ int   g_eidx[NE];

// ---------------- CSR build ----------------
__global__ void k_zero(int n) {
    int i = blockIdx.x * blockDim.x + threadIdx.x;
    if (i < n) { g_cnt[i] = 0; g_fill[i] = 0; }
}

__global__ void k_count(const int* __restrict__ dst, int E) {
    int i = blockIdx.x * blockDim.x + threadIdx.x;
    if (i < E) atomicAdd(&g_cnt[dst[i]], 1);
}

// single-block exclusive scan of g_cnt -> g_row (n <= a few hundred K)
__global__ __launch_bounds__(1024)
void k_scan(int n) {
    __shared__ int sh[1024];
    __shared__ int carry;
    int tid = threadIdx.x;
    if (tid == 0) carry = 0;
    __syncthreads();
    for (int base = 0; base < n; base += 1024) {
        int i = base + tid;
        int v = (i < n) ? g_cnt[i] : 0;
        sh[tid] = v;
        __syncthreads();
        #pragma unroll
        for (int off = 1; off < 1024; off <<= 1) {
            int t = (tid >= off) ? sh[tid - off] : 0;
            __syncthreads();
            sh[tid] += t;
            __syncthreads();
        }
        if (i < n) g_row[i] = sh[tid] - v + carry;   // exclusive
        int total = sh[1023];
        __syncthreads();
        if (tid == 0) carry += total;
        __syncthreads();
    }
    if (tid == 0) g_row[n] = carry;
}

__global__ void k_scatter(const int* __restrict__ src, const int* __restrict__ dst, int E) {
    int i = blockIdx.x * blockDim.x + threadIdx.x;
    if (i >= E) return;
    int d = dst[i];
    int pos = g_row[d] + atomicAdd(&g_fill[d], 1);
    g_eidx[pos] = src[i];
}

// ---------------- tf32 helpers ----------------
__device__ __forceinline__ unsigned cvt_tf32(float x) {
    unsigned r; asm("cvt.rna.tf32.f32 %0, %1;" : "=r"(r) : "f"(x)); return r;
}
__device__ __forceinline__ void mma_tf32(float c[4], unsigned a0, unsigned a1,
                                         unsigned a2, unsigned a3,
                                         unsigned b0, unsigned b1) {
    asm volatile(
        "mma.sync.aligned.m16n8k8.row.col.f32.tf32.tf32.f32 "
        "{%0,%1,%2,%3}, {%4,%5,%6,%7}, {%8,%9}, {%0,%1,%2,%3};"
        : "+f"(c[0]), "+f"(c[1]), "+f"(c[2]), "+f"(c[3])
        : "r"(a0), "r"(a1), "r"(a2), "r"(a3), "r"(b0), "r"(b1));
}

// ================= big input GEMMs: 3xTF32, conflict-free smem =================
#define AMLD 36
#define BNLD 132

struct MmaSmem {
    unsigned Ahi[128][AMLD];
    unsigned Alo[128][AMLD];
    unsigned Bhi[32][BNLD];
    unsigned Blo[32][BNLD];
};
#define MMA_SMEM_BYTES ((int)sizeof(MmaSmem))

__global__ __launch_bounds__(256, 2)
void k_mma_gemm(const float* __restrict__ Ai, const float* __restrict__ At,
                const float* __restrict__ Bi, const float* __restrict__ Bt,
                float* __restrict__ Ci, float* __restrict__ Ct,
                int M, int Ki, int Kt) {
    extern __shared__ char smem_raw[];
    MmaSmem& s = *reinterpret_cast<MmaSmem*>(smem_raw);
    int sel = blockIdx.y;
    const float* A = sel ? At : Ai;
    const float* B = sel ? Bt : Bi;
    float*       C = sel ? Ct : Ci;
    int K = sel ? Kt : Ki;

    int tid  = threadIdx.x;
    int warp = tid >> 5, lane = tid & 31;
    int wm = warp & 1;
    int wn = warp >> 1;
    int grp = lane >> 2, q = lane & 3;
    int m0 = blockIdx.x * 128;

    float acc[4][4][4];
    #pragma unroll
    for (int i = 0; i < 4; ++i)
        #pragma unroll
        for (int j = 0; j < 4; ++j)
            #pragma unroll
            for (int k = 0; k < 4; ++k) acc[i][j][k] = 0.f;

    #pragma unroll 1
    for (int k0 = 0; k0 < K; k0 += 32) {
        #pragma unroll
        for (int i = 0; i < 4; ++i) {
            int f4 = tid + i * 256;
            int r = f4 >> 3, c4 = f4 & 7;
            float4 v = make_float4(0.f, 0.f, 0.f, 0.f);
            if (m0 + r < M) v = *(const float4*)&A[(size_t)(m0 + r) * K + k0 + c4 * 4];
            float vv[4] = {v.x, v.y, v.z, v.w};
            unsigned hi4[4], lo4[4];
            #pragma unroll
            for (int j = 0; j < 4; ++j) {
                hi4[j] = cvt_tf32(vv[j]);
                lo4[j] = cvt_tf32(vv[j] - __uint_as_float(hi4[j]));
            }
            *(uint4*)&s.Ahi[r][c4 * 4] = make_uint4(hi4[0], hi4[1], hi4[2], hi4[3]);
            *(uint4*)&s.Alo[r][c4 * 4] = make_uint4(lo4[0], lo4[1], lo4[2], lo4[3]);
        }
        #pragma unroll
        for (int i = 0; i < 4; ++i) {
            int f4 = tid + i * 256;
            int kk = f4 >> 5, c = f4 & 31;
            float4 v = *(const float4*)&B[(size_t)(k0 + kk) * 128 + c * 4];
            float vv[4] = {v.x, v.y, v.z, v.w};
            unsigned hi4[4], lo4[4];
            #pragma unroll
            for (int j = 0; j < 4; ++j) {
                hi4[j] = cvt_tf32(vv[j]);
                lo4[j] = cvt_tf32(vv[j] - __uint_as_float(hi4[j]));
            }
            *(uint4*)&s.Bhi[kk][c * 4] = make_uint4(hi4[0], hi4[1], hi4[2], hi4[3]);
            *(uint4*)&s.Blo[kk][c * 4] = make_uint4(lo4[0], lo4[1], lo4[2], lo4[3]);
        }
        __syncthreads();

        #pragma unroll
        for (int kc = 0; kc < 4; ++kc) {
            int kq = kc * 8 + q;
            unsigned af[4][4], bh[4][2], bl[4][2];
            #pragma unroll
            for (int mt = 0; mt < 4; ++mt) {
                int m = wm * 64 + mt * 16 + grp;
                af[mt][0] = s.Ahi[m][kq];
                af[mt][1] = s.Ahi[m + 8][kq];
                af[mt][2] = s.Ahi[m][kq + 4];
                af[mt][3] = s.Ahi[m + 8][kq + 4];
            }
            #pragma unroll
            for (int nt = 0; nt < 4; ++nt) {
                int n = wn * 32 + nt * 8 + grp;
                bh[nt][0] = s.Bhi[kq][n];  bh[nt][1] = s.Bhi[kq + 4][n];
                bl[nt][0] = s.Blo[kq][n];  bl[nt][1] = s.Blo[kq + 4][n];
            }
            #pragma unroll
            for (int mt = 0; mt < 4; ++mt)
                #pragma unroll
                for (int nt = 0; nt < 4; ++nt) {
                    mma_tf32(acc[mt][nt], af[mt][0], af[mt][1], af[mt][2], af[mt][3],
                             bh[nt][0], bh[nt][1]);
                    mma_tf32(acc[mt][nt], af[mt][0], af[mt][1], af[mt][2], af[mt][3],
                             bl[nt][0], bl[nt][1]);
                }
            #pragma unroll
            for (int mt = 0; mt < 4; ++mt) {
                int m = wm * 64 + mt * 16 + grp;
                af[mt][0] = s.Alo[m][kq];
                af[mt][1] = s.Alo[m + 8][kq];
                af[mt][2] = s.Alo[m][kq + 4];
                af[mt][3] = s.Alo[m + 8][kq + 4];
            }
            #pragma unroll
            for (int mt = 0; mt < 4; ++mt)
                #pragma unroll
                for (int nt = 0; nt < 4; ++nt)
                    mma_tf32(acc[mt][nt], af[mt][0], af[mt][1], af[mt][2], af[mt][3],
                             bh[nt][0], bh[nt][1]);
        }
        __syncthreads();
    }

    #pragma unroll
    for (int mt = 0; mt < 4; ++mt) {
        int m = m0 + wm * 64 + mt * 16 + grp;
        #pragma unroll
        for (int nt = 0; nt < 4; ++nt) {
            int n = wn * 32 + nt * 8 + 2 * q;
            if (m < M)
                *(float2*)&C[(size_t)m * 128 + n] = make_float2(acc[mt][nt][0], acc[mt][nt][1]);
            if (m + 8 < M)
                *(float2*)&C[(size_t)(m + 8) * 128 + n] = make_float2(acc[mt][nt][2], acc[mt][nt][3]);
        }
    }
}

// ================= fused per-node pipeline: tensor-core version =================
#define XLD 132

struct SmemN {
    float E[32][XLD];
    float A[32][XLD];
    float B[32][XLD];
    float H[32][XLD];
    float red[32][8][2];
    float g[32];
};
#define NODE_SMEM_BYTES ((int)sizeof(SmemN))

__device__ __forceinline__ void zacc(float acc[2][2][4]) {
    #pragma unroll
    for (int i = 0; i < 2; ++i)
        #pragma unroll
        for (int j = 0; j < 2; ++j)
            #pragma unroll
            for (int k = 0; k < 4; ++k) acc[i][j][k] = 0.f;
}

__device__ __forceinline__ void npass1(const float (*__restrict__ X)[XLD],
                                       const float* __restrict__ W,
                                       float acc[2][2][4], int n0, int grp, int q) {
    #pragma unroll 4
    for (int kc = 0; kc < 16; ++kc) {
        int k0 = kc * 8;
        unsigned a[2][4];
        #pragma unroll
        for (int mt = 0; mt < 2; ++mt) {
            a[mt][0] = cvt_tf32(X[mt * 16 + grp    ][k0 + q]);
            a[mt][1] = cvt_tf32(X[mt * 16 + grp + 8][k0 + q]);
            a[mt][2] = cvt_tf32(X[mt * 16 + grp    ][k0 + q + 4]);
            a[mt][3] = cvt_tf32(X[mt * 16 + grp + 8][k0 + q + 4]);
        }
        unsigned b[2][2];
        #pragma unroll
        for (int nt = 0; nt < 2; ++nt) {
            b[nt][0] = cvt_tf32(__ldg(&W[(k0 + q)     * 128 + n0 + nt * 8 + grp]));
            b[nt][1] = cvt_tf32(__ldg(&W[(k0 + q + 4) * 128 + n0 + nt * 8 + grp]));
        }
        #pragma unroll
        for (int mt = 0; mt < 2; ++mt)
            #pragma unroll
            for (int nt = 0; nt < 2; ++nt)
                mma_tf32(acc[mt][nt], a[mt][0], a[mt][1], a[mt][2], a[mt][3],
                         b[nt][0], b[nt][1]);
    }
}

__device__ __forceinline__ void npass3(const float (*__restrict__ X)[XLD],
                                       const float* __restrict__ W,
                                       float acc[2][2][4], int n0, int grp, int q) {
    #pragma unroll 2
    for (int kc = 0; kc < 16; ++kc) {
        int k0 = kc * 8;
        unsigned ah[2][4], al[2][4];
        #pragma unroll
        for (int mt = 0; mt < 2; ++mt) {
            float x0 = X[mt * 16 + grp    ][k0 + q];
            float x1 = X[mt * 16 + grp + 8][k0 + q];
            float x2 = X[mt * 16 + grp    ][k0 + q + 4];
            float x3 = X[mt * 16 + grp + 8][k0 + q + 4];
            ah[mt][0] = cvt_tf32(x0); al[mt][0] = cvt_tf32(x0 - __uint_as_float(ah[mt][0]));
            ah[mt][1] = cvt_tf32(x1); al[mt][1] = cvt_tf32(x1 - __uint_as_float(ah[mt][1]));
            ah[mt][2] = cvt_tf32(x2); al[mt][2] = cvt_tf32(x2 - __uint_as_float(ah[mt][2]));
            ah[mt][3] = cvt_tf32(x3); al[mt][3] = cvt_tf32(x3 - __uint_as_float(ah[mt][3]));
        }
        unsigned bh[2][2], bl[2][2];
        #pragma unroll
        for (int nt = 0; nt < 2; ++nt) {
            float w0 = __ldg(&W[(k0 + q)     * 128 + n0 + nt * 8 + grp]);
            float w1 = __ldg(&W[(k0 + q + 4) * 128 + n0 + nt * 8 + grp]);
            bh[nt][0] = cvt_tf32(w0); bl[nt][0] = cvt_tf32(w0 - __uint_as_float(bh[nt][0]));
            bh[nt][1] = cvt_tf32(w1); bl[nt][1] = cvt_tf32(w1 - __uint_as_float(bh[nt][1]));
        }
        #pragma unroll
        for (int mt = 0; mt < 2; ++mt)
            #pragma unroll
            for (int nt = 0; nt < 2; ++nt) {
                mma_tf32(acc[mt][nt], ah[mt][0], ah[mt][1], ah[mt][2], ah[mt][3],
                         bh[nt][0], bh[nt][1]);
                mma_tf32(acc[mt][nt], ah[mt][0], ah[mt][1], ah[mt][2], ah[mt][3],
                         bl[nt][0], bl[nt][1]);
                mma_tf32(acc[mt][nt], al[mt][0], al[mt][1], al[mt][2], al[mt][3],
                         bh[nt][0], bh[nt][1]);
            }
    }
}

__device__ __forceinline__ void relu_store(SmemN& s, float acc[2][2][4],
                                           const float* __restrict__ bp,
                                           int n0, int grp, int q) {
    #pragma unroll
    for (int nt = 0; nt < 2; ++nt) {
        int col = n0 + nt * 8 + 2 * q;
        float2 b = __ldg((const float2*)&bp[col]);
        #pragma unroll
        for (int mt = 0; mt < 2; ++mt) {
            int r1 = mt * 16 + grp;
            s.H[r1][col]     = fmaxf(acc[mt][nt][0] + b.x, 0.f);
            s.H[r1][col + 1] = fmaxf(acc[mt][nt][1] + b.y, 0.f);
            s.H[r1 + 8][col]     = fmaxf(acc[mt][nt][2] + b.x, 0.f);
            s.H[r1 + 8][col + 1] = fmaxf(acc[mt][nt][3] + b.y, 0.f);
        }
    }
}

__device__ __forceinline__ void gate_finish(SmemN& s, float acc[2][2][4],
                                            const float* __restrict__ b2p,
                                            const float* __restrict__ w3p,
                                            const float* __restrict__ b3p,
                                            int n0, int grp, int q, int warp, int tid) {
    float part[4] = {0.f, 0.f, 0.f, 0.f};
    #pragma unroll
    for (int nt = 0; nt < 2; ++nt) {
        int col = n0 + nt * 8 + 2 * q;
        float2 b2 = __ldg((const float2*)&b2p[col]);
        float2 w3 = __ldg((const float2*)&w3p[col]);
        #pragma unroll
        for (int mt = 0; mt < 2; ++mt) {
            part[mt * 2 + 0] += fmaxf(acc[mt][nt][0] + b2.x, 0.f) * w3.x
                              + fmaxf(acc[mt][nt][1] + b2.y, 0.f) * w3.y;
            part[mt * 2 + 1] += fmaxf(acc[mt][nt][2] + b2.x, 0.f) * w3.x
                              + fmaxf(acc[mt][nt][3] + b2.y, 0.f) * w3.y;
        }
    }
    #pragma unroll
    for (int i = 0; i < 4; ++i) {
        part[i] += __shfl_xor_sync(0xffffffffu, part[i], 1);
        part[i] += __shfl_xor_sync(0xffffffffu, part[i], 2);
    }
    if (q == 0) {
        #pragma unroll
        for (int mt = 0; mt < 2; ++mt) {
            s.red[mt * 16 + grp][warp][0]     = part[mt * 2 + 0];
            s.red[mt * 16 + grp + 8][warp][0] = part[mt * 2 + 1];
        }
    }
    __syncthreads();
    if (tid < 32) {
        float v = 0.f;
        #pragma unroll
        for (int w = 0; w < 8; ++w) v += s.red[tid][w][0];
        s.g[tid] = 1.f / (1.f + expf(-(v + __ldg(b3p))));
    }
    __syncthreads();
}

__global__ __launch_bounds__(256, 3)
void k_node(const int* __restrict__ node_id, const float* __restrict__ emb,
            const float* __restrict__ iW1, const float* __restrict__ ib1,
            const float* __restrict__ iW2, const float* __restrict__ ib2,
            const float* __restrict__ iW3, const float* __restrict__ ib3,
            const float* __restrict__ tW1, const float* __restrict__ tb1,
            const float* __restrict__ tW2, const float* __restrict__ tb2,
            const float* __restrict__ tW3, const float* __restrict__ tb3,
            const float* __restrict__ cW,  const float* __restrict__ cb,
            const float* __restrict__ fW,  const float* __restrict__ attn_a,
            int N) {
    extern __shared__ char smem_raw[];
    SmemN& s = *reinterpret_cast<SmemN*>(smem_raw);
    int tid = threadIdx.x;
    int warp = tid >> 5, lane = tid & 31;
    int grp = lane >> 2, q = lane & 3;
    int n0 = warp * 16;
    int r8 = tid >> 5, c32 = tid & 31;
    int base = blockIdx.x * 32;

    #pragma unroll
    for (int it = 0; it < 4; ++it) {
        int idx = tid + it * 256;
        int n = idx >> 5, c4 = idx & 31;
        int gn = base + n;
        int nid = (gn < N) ? __ldg(&node_id[gn]) : 0;
        *(float4*)&s.E[n][c4 * 4] = *(const float4*)&emb[(size_t)nid * 128 + c4 * 4];
        float4 iv = make_float4(0.f, 0.f, 0.f, 0.f);
        float4 tv = make_float4(0.f, 0.f, 0.f, 0.f);
        if (gn < N) {
            iv = *(const float4*)&g_img_f[(size_t)gn * 128 + c4 * 4];
            tv = *(const float4*)&g_txt_f[(size_t)gn * 128 + c4 * 4];
        }
        *(float4*)&s.A[n][c4 * 4] = iv;
        *(float4*)&s.B[n][c4 * 4] = tv;
    }
    __syncthreads();

    float acc[2][2][4];

    zacc(acc);
    npass1(s.E, iW1, acc, n0, grp, q);
    npass1(s.A, iW1 + 128 * 128, acc, n0, grp, q);
    relu_store(s, acc, ib1, n0, grp, q);
    __syncthreads();

    zacc(acc);
    npass1(s.H, iW2, acc, n0, grp, q);
    gate_finish(s, acc, ib2, iW3, ib3, n0, grp, q, warp, tid);

    #pragma unroll
    for (int i = 0; i < 4; ++i) {
        float gv = s.g[r8 * 4 + i];
        float4 av = *(const float4*)&s.A[r8 * 4 + i][c32 * 4];
        float4 ev = *(const float4*)&s.E[r8 * 4 + i][c32 * 4];
        av.x = gv * av.x + (1.f - gv) * ev.x;
        av.y = gv * av.y + (1.f - gv) * ev.y;
        av.z = gv * av.z + (1.f - gv) * ev.z;
        av.w = gv * av.w + (1.f - gv) * ev.w;
        *(float4*)&s.A[r8 * 4 + i][c32 * 4] = av;
    }

    zacc(acc);
    npass1(s.E, tW1, acc, n0, grp, q);
    npass1(s.B, tW1 + 128 * 128, acc, n0, grp, q);
    relu_store(s, acc, tb1, n0, grp, q);
    __syncthreads();

    zacc(acc);
    npass1(s.H, tW2, acc, n0, grp, q);
    gate_finish(s, acc, tb2, tW3, tb3, n0, grp, q, warp, tid);

    #pragma unroll
    for (int i = 0; i < 4; ++i) {
        float gv = s.g[r8 * 4 + i];
        float4 bv = *(const float4*)&s.B[r8 * 4 + i][c32 * 4];
        float4 ev = *(const float4*)&s.E[r8 * 4 + i][c32 * 4];
        bv.x = gv * bv.x + (1.f - gv) * ev.x;
        bv.y = gv * bv.y + (1.f - gv) * ev.y;
        bv.z = gv * bv.z + (1.f - gv) * ev.z;
        bv.w = gv * bv.w + (1.f - gv) * ev.w;
        *(float4*)&s.B[r8 * 4 + i][c32 * 4] = bv;
    }
    __syncthreads();

    zacc(acc);
    npass3(s.A, cW, acc, n0, grp, q);
    npass3(s.B, cW + 128 * 128, acc, n0, grp, q);
    {
        #pragma unroll
        for (int nt = 0; nt < 2; ++nt) {
            int col = n0 + nt * 8 + 2 * q;
            float2 cbv = __ldg((const float2*)&cb[col]);
            #pragma unroll
            for (int mt = 0; mt < 2; ++mt) {
                int r1 = mt * 16 + grp, r2 = r1 + 8;
                float g0 = acc[mt][nt][0] + cbv.x;
                float g1 = acc[mt][nt][1] + cbv.y;
                float g2 = acc[mt][nt][2] + cbv.x;
                float g3 = acc[mt][nt][3] + cbv.y;
                float2 av1 = *(const float2*)&s.A[r1][col];
                float2 bv1 = *(const float2*)&s.B[r1][col];
                float2 av2 = *(const float2*)&s.A[r2][col];
                float2 bv2 = *(const float2*)&s.B[r2][col];
                s.H[r1][col]     = g0 * av1.x + (1.f - g0) * bv1.x;
                s.H[r1][col + 1] = g1 * av1.y + (1.f - g1) * bv1.y;
                s.H[r2][col]     = g2 * av2.x + (1.f - g2) * bv2.x;
                s.H[r2][col + 1] = g3 * av2.y + (1.f - g3) * bv2.y;
            }
        }
    }
    __syncthreads();

    zacc(acc);
    npass3(s.H, fW, acc, n0, grp, q);
    {
        float p1[4] = {0.f, 0.f, 0.f, 0.f};
        float p2[4] = {0.f, 0.f, 0.f, 0.f};
        #pragma unroll
        for (int nt = 0; nt < 2; ++nt) {
            int col = n0 + nt * 8 + 2 * q;
            float2 a1 = __ldg((const float2*)&attn_a[col]);
            float2 a2 = __ldg((const float2*)&attn_a[128 + col]);
            #pragma unroll
            for (int mt = 0; mt < 2; ++mt) {
                int r1 = mt * 16 + grp, r2 = r1 + 8;
                int g1_ = base + r1, g2_ = base + r2;
                if (g1_ < N)
                    *(float2*)&g_z[(size_t)g1_ * 128 + col] =
                        make_float2(acc[mt][nt][0], acc[mt][nt][1]);
                if (g2_ < N)
                    *(float2*)&g_z[(size_t)g2_ * 128 + col] =
                        make_float2(acc[mt][nt][2], acc[mt][nt][3]);
                p1[mt * 2 + 0] += acc[mt][nt][0] * a1.x + acc[mt][nt][1] * a1.y;
                p1[mt * 2 + 1] += acc[mt][nt][2] * a1.x + acc[mt][nt][3] * a1.y;
                p2[mt * 2 + 0] += acc[mt][nt][0] * a2.x + acc[mt][nt][1] * a2.y;
                p2[mt * 2 + 1] += acc[mt][nt][2] * a2.x + acc[mt][nt][3] * a2.y;
            }
        }
        #pragma unroll
        for (int i = 0; i < 4; ++i) {
            p1[i] += __shfl_xor_sync(0xffffffffu, p1[i], 1);
            p1[i] += __shfl_xor_sync(0xffffffffu, p1[i], 2);
            p2[i] += __shfl_xor_sync(0xffffffffu, p2[i], 1);
            p2[i] += __shfl_xor_sync(0xffffffffu, p2[i], 2);
        }
        if (q == 0) {
            #pragma unroll
            for (int mt = 0; mt < 2; ++mt) {
                s.red[mt * 16 + grp][warp][0]     = p1[mt * 2 + 0];
                s.red[mt * 16 + grp + 8][warp][0] = p1[mt * 2 + 1];
                s.red[mt * 16 + grp][warp][1]     = p2[mt * 2 + 0];
                s.red[mt * 16 + grp + 8][warp][1] = p2[mt * 2 + 1];
            }
        }
        __syncthreads();
        if (tid < 32) {
            float v1 = 0.f, v2 = 0.f;
            #pragma unroll
            for (int w = 0; w < 8; ++w) { v1 += s.red[tid][w][0]; v2 += s.red[tid][w][1]; }
            int gn = base + tid;
            if (gn < N) { g_esrc[gn] = v1; g_edst[gn] = v2; }
        }
    }
}

// ---------------- CSR aggregate: warp per dst node, no atomics ----------------
__global__ __launch_bounds__(256)
void k_agg(float* __restrict__ out, int N) {
    int w = (int)((blockIdx.x * (size_t)blockDim.x + threadIdx.x) >> 5);
    int lane = threadIdx.x & 31;
    if (w >= N) return;
    int beg = g_row[w], end = g_row[w + 1];
    float ed = g_edst[w];

    // phase 1: exact max over incoming edges (lane-strided)
    float m = -CUDART_INF_F;
    for (int i = beg + lane; i < end; i += 32) {
        float e = g_esrc[g_eidx[i]] + ed;
        e = (e >= 0.f) ? e : 0.01f * e;
        m = fmaxf(m, e);
    }
    #pragma unroll
    for (int off = 16; off > 0; off >>= 1)
        m = fmaxf(m, __shfl_xor_sync(0xffffffffu, m, off));

    // phase 2: chunk of 32 edges; each lane computes one weight, broadcast via shfl
    float4 acc = make_float4(0.f, 0.f, 0.f, 0.f);
    float denom = 0.f;
    for (int basei = beg; basei < end; basei += 32) {
        int idx = basei + lane;
        float wgt = 0.f; int sj = 0;
        if (idx < end) {
            sj = g_eidx[idx];
            float e = g_esrc[sj] + ed;
            e = (e >= 0.f) ? e : 0.01f * e;
            wgt = expf(e - m);
        }
        int cnt = min(32, end - basei);
        for (int j = 0; j < cnt; ++j) {
            float wj = __shfl_sync(0xffffffffu, wgt, j);
            int   s_ = __shfl_sync(0xffffffffu, sj, j);
            float4 zv = __ldg((const float4*)&g_z[(size_t)s_ * 128 + lane * 4]);
            acc.x = fmaf(wj, zv.x, acc.x);
            acc.y = fmaf(wj, zv.y, acc.y);
            acc.z = fmaf(wj, zv.z, acc.z);
            acc.w = fmaf(wj, zv.w, acc.w);
            denom += wj;
        }
    }
    float inv = (denom > 1e-20f) ? 1.f / denom : 0.f;
    acc.x *= inv; acc.y *= inv; acc.z *= inv; acc.w *= inv;
    *(float4*)&out[(size_t)w * 128 + lane * 4] = acc;
}

// ---------------- launch ----------------
extern "C" void kernel_launch(void* const* d_in, const int* in_sizes, int n_in,
                              void* d_out, int out_size) {
    const int*   node_id = (const int*)  d_in[0];
    const float* img_h   = (const float*)d_in[1];
    const float* txt_h   = (const float*)d_in[2];
    const int*   src     = (const int*)  d_in[3];
    const int*   dst     = (const int*)  d_in[4];
    const float* emb     = (const float*)d_in[5];
    const float* W_img   = (const float*)d_in[6];
    const float* iW1     = (const float*)d_in[7];
    const float* ib1     = (const float*)d_in[8];
    const float* iW2     = (const float*)d_in[9];
    const float* ib2     = (const float*)d_in[10];
    const float* iW3     = (const float*)d_in[11];
    const float* ib3     = (const float*)d_in[12];
    const float* W_txt   = (const float*)d_in[13];
    const float* tW1     = (const float*)d_in[14];
    const float* tb1     = (const float*)d_in[15];
    const float* tW2     = (const float*)d_in[16];
    const float* tb2     = (const float*)d_in[17];
    const float* tW3     = (const float*)d_in[18];
    const float* tb3     = (const float*)d_in[19];
    const float* cW      = (const float*)d_in[20];
    const float* cb      = (const float*)d_in[21];
    const float* fW      = (const float*)d_in[22];
    const float* attn_a  = (const float*)d_in[23];

    int N = in_sizes[0];
    int E = in_sizes[3];
    int IMG_D = in_sizes[1] / N;
    int TXT_D = in_sizes[2] / N;
    float* out = (float*)d_out;

    float *p_img_f, *p_txt_f;
    cudaGetSymbolAddress((void**)&p_img_f, g_img_f);
    cudaGetSymbolAddress((void**)&p_txt_f, g_txt_f);

    cudaFuncSetAttribute(k_node, cudaFuncAttributeMaxDynamicSharedMemorySize, NODE_SMEM_BYTES);
    cudaFuncSetAttribute(k_mma_gemm, cudaFuncAttributeMaxDynamicSharedMemorySize, MMA_SMEM_BYTES);

    // CSR build (independent of GEMM/node results)
    k_zero<<<(N + 255) / 256, 256>>>(N);
    k_count<<<(E + 255) / 256, 256>>>(dst, E);
    k_scan<<<1, 1024>>>(N);
    k_scatter<<<(E + 255) / 256, 256>>>(src, dst, E);

    dim3 ggrid((N + 127) / 128, 2);
    k_mma_gemm<<<ggrid, 256, MMA_SMEM_BYTES>>>(img_h, txt_h, W_img, W_txt,
                                               p_img_f, p_txt_f, N, IMG_D, TXT_D);

    k_node<<<(N + 31) / 32, 256, NODE_SMEM_BYTES>>>(
        node_id, emb,
        iW1, ib1, iW2, ib2, iW3, ib3,
        tW1, tb1, tW2, tb2, tW3, tb3,
        cW, cb, fW, attn_a, N);

    k_agg<<<(N * 32 + 255) / 256, 256>>>(out, N);
}

// round 6
// speedup vs baseline: 1.3546x; 1.3546x over previous
#include <cuda_runtime.h>
#include <math_constants.h>
#include <cuda_bf16.h>

#define NN 50000
#define NE 800000
#define HID 128

// ---------------- scratch ----------------
__device__ float g_img_f[NN * HID];
__device__ float g_txt_f[NN * HID];
__device__ float g_z[NN * HID];
__device__ float g_esrc[NN];
__device__ float g_edst[NN];
__device__ int   g_cnt[NN];
__device__ int   g_fill[NN];
__device__ int   g_row[NN + 1];
__device__ int   g_eidx[NE];

// ---------------- CSR build ----------------
__global__ void k_zero(int n) {
    int i = blockIdx.x * blockDim.x + threadIdx.x;
    if (i < n) { g_cnt[i] = 0; g_fill[i] = 0; }
}

__global__ void k_count(const int* __restrict__ dst, int E) {
    int i = blockIdx.x * blockDim.x + threadIdx.x;
    if (i < E) atomicAdd(&g_cnt[dst[i]], 1);
}

__global__ __launch_bounds__(1024)
void k_scan(int n) {
    __shared__ int sh[1024];
    __shared__ int carry;
    int tid = threadIdx.x;
    if (tid == 0) carry = 0;
    __syncthreads();
    for (int base = 0; base < n; base += 1024) {
        int i = base + tid;
        int v = (i < n) ? g_cnt[i] : 0;
        sh[tid] = v;
        __syncthreads();
        #pragma unroll
        for (int off = 1; off < 1024; off <<= 1) {
            int t = (tid >= off) ? sh[tid - off] : 0;
            __syncthreads();
            sh[tid] += t;
            __syncthreads();
        }
        if (i < n) g_row[i] = sh[tid] - v + carry;   // exclusive
        int total = sh[1023];
        __syncthreads();
        if (tid == 0) carry += total;
        __syncthreads();
    }
    if (tid == 0) g_row[n] = carry;
}

__global__ void k_scatter(const int* __restrict__ src, const int* __restrict__ dst, int E) {
    int i = blockIdx.x * blockDim.x + threadIdx.x;
    if (i >= E) return;
    int d = dst[i];
    int pos = g_row[d] + atomicAdd(&g_fill[d], 1);
    g_eidx[pos] = src[i];
}

// ---------------- mma helpers ----------------
__device__ __forceinline__ unsigned cvt_tf32(float x) {
    unsigned r; asm("cvt.rna.tf32.f32 %0, %1;" : "=r"(r) : "f"(x)); return r;
}
__device__ __forceinline__ void mma_tf32(float c[4], unsigned a0, unsigned a1,
                                         unsigned a2, unsigned a3,
                                         unsigned b0, unsigned b1) {
    asm volatile(
        "mma.sync.aligned.m16n8k8.row.col.f32.tf32.tf32.f32 "
        "{%0,%1,%2,%3}, {%4,%5,%6,%7}, {%8,%9}, {%0,%1,%2,%3};"
        : "+f"(c[0]), "+f"(c[1]), "+f"(c[2]), "+f"(c[3])
        : "r"(a0), "r"(a1), "r"(a2), "r"(a3), "r"(b0), "r"(b1));
}
// pack two floats into bf16x2: lo-half = first arg, hi-half = second
__device__ __forceinline__ unsigned pkbf2(float lo, float hi) {
    unsigned r; asm("cvt.rn.bf16x2.f32 %0, %1, %2;" : "=r"(r) : "f"(hi), "f"(lo));
    return r;
}
__device__ __forceinline__ float bf16_rn(float x) {
    return __bfloat162float(__float2bfloat16_rn(x));
}
__device__ __forceinline__ void mma_bf16(float c[4], unsigned a0, unsigned a1,
                                         unsigned a2, unsigned a3,
                                         unsigned b0, unsigned b1) {
    asm volatile(
        "mma.sync.aligned.m16n8k16.row.col.f32.bf16.bf16.f32 "
        "{%0,%1,%2,%3}, {%4,%5,%6,%7}, {%8,%9}, {%0,%1,%2,%3};"
        : "+f"(c[0]), "+f"(c[1]), "+f"(c[2]), "+f"(c[3])
        : "r"(a0), "r"(a1), "r"(a2), "r"(a3), "r"(b0), "r"(b1));
}

// ================= big input GEMMs: split-bf16 (hh+hl+lh), m16n8k16 =================
// BK=32 floats = 16 bf16-pairs per tile.
// A tiles [m][pair] LD=20 (bank = 20*grp+q : all-distinct for frag loads)
// B tiles [pair][n] LD=136 (bank = 8q+grp : all-distinct)
#define APLD 20
#define BPLD 136

struct MmaSmem {
    unsigned Ahi[128][APLD];
    unsigned Alo[128][APLD];
    unsigned Bhi[16][BPLD];
    unsigned Blo[16][BPLD];
};
#define MMA_SMEM_BYTES ((int)sizeof(MmaSmem))

__global__ __launch_bounds__(256, 2)
void k_mma_gemm(const float* __restrict__ Ai, const float* __restrict__ At,
                const float* __restrict__ Bi, const float* __restrict__ Bt,
                float* __restrict__ Ci, float* __restrict__ Ct,
                int M, int Ki, int Kt) {
    extern __shared__ char smem_raw[];
    MmaSmem& s = *reinterpret_cast<MmaSmem*>(smem_raw);
    int sel = blockIdx.y;
    const float* A = sel ? At : Ai;
    const float* B = sel ? Bt : Bi;
    float*       C = sel ? Ct : Ci;
    int K = sel ? Kt : Ki;

    int tid  = threadIdx.x;
    int warp = tid >> 5, lane = tid & 31;
    int wm = warp & 1;          // 64-row slab
    int wn = warp >> 1;         // 32-col slab
    int grp = lane >> 2, q = lane & 3;
    int m0 = blockIdx.x * 128;

    float acc[4][4][4];
    #pragma unroll
    for (int i = 0; i < 4; ++i)
        #pragma unroll
        for (int j = 0; j < 4; ++j)
            #pragma unroll
            for (int k = 0; k < 4; ++k) acc[i][j][k] = 0.f;

    #pragma unroll 1
    for (int k0 = 0; k0 < K; k0 += 32) {
        // ---- stage A tile 128x32 floats -> hi/lo bf16 pairs [m][16] ----
        #pragma unroll
        for (int i = 0; i < 4; ++i) {
            int f4 = tid + i * 256;           // 0..1023
            int r = f4 >> 3, c4 = f4 & 7;     // row r, k-group (4 floats)
            float4 v = make_float4(0.f, 0.f, 0.f, 0.f);
            if (m0 + r < M) v = *(const float4*)&A[(size_t)(m0 + r) * K + k0 + c4 * 4];
            float hx = bf16_rn(v.x), hy = bf16_rn(v.y);
            float hz = bf16_rn(v.z), hw = bf16_rn(v.w);
            uint2 hp = make_uint2(pkbf2(v.x, v.y), pkbf2(v.z, v.w));
            uint2 lp = make_uint2(pkbf2(v.x - hx, v.y - hy), pkbf2(v.z - hz, v.w - hw));
            *(uint2*)&s.Ahi[r][2 * c4] = hp;
            *(uint2*)&s.Alo[r][2 * c4] = lp;
        }
        // ---- stage B tile 32x128 floats -> hi/lo pairs [16][128] ----
        #pragma unroll
        for (int i = 0; i < 8; ++i) {
            int idx = tid + i * 256;          // 0..2047
            int kp = idx >> 7, c = idx & 127;
            float f0 = B[(size_t)(k0 + 2 * kp) * 128 + c];
            float f1 = B[(size_t)(k0 + 2 * kp + 1) * 128 + c];
            float h0 = bf16_rn(f0), h1 = bf16_rn(f1);
            s.Bhi[kp][c] = pkbf2(f0, f1);
            s.Blo[kp][c] = pkbf2(f0 - h0, f1 - h1);
        }
        __syncthreads();

        #pragma unroll
        for (int sstep = 0; sstep < 2; ++sstep) {
            int p = sstep * 8 + q;            // pair index for this lane
            unsigned af[4][4], bh[4][2], bl[4][2];
            #pragma unroll
            for (int mt = 0; mt < 4; ++mt) {
                int m = wm * 64 + mt * 16 + grp;
                af[mt][0] = s.Ahi[m][p];
                af[mt][1] = s.Ahi[m + 8][p];
                af[mt][2] = s.Ahi[m][p + 4];
                af[mt][3] = s.Ahi[m + 8][p + 4];
            }
            #pragma unroll
            for (int nt = 0; nt < 4; ++nt) {
                int n = wn * 32 + nt * 8 + grp;
                bh[nt][0] = s.Bhi[p][n];      bh[nt][1] = s.Bhi[p + 4][n];
                bl[nt][0] = s.Blo[p][n];      bl[nt][1] = s.Blo[p + 4][n];
            }
            // hh + hl
            #pragma unroll
            for (int mt = 0; mt < 4; ++mt)
                #pragma unroll
                for (int nt = 0; nt < 4; ++nt) {
                    mma_bf16(acc[mt][nt], af[mt][0], af[mt][1], af[mt][2], af[mt][3],
                             bh[nt][0], bh[nt][1]);
                    mma_bf16(acc[mt][nt], af[mt][0], af[mt][1], af[mt][2], af[mt][3],
                             bl[nt][0], bl[nt][1]);
                }
            // lh
            #pragma unroll
            for (int mt = 0; mt < 4; ++mt) {
                int m = wm * 64 + mt * 16 + grp;
                af[mt][0] = s.Alo[m][p];
                af[mt][1] = s.Alo[m + 8][p];
                af[mt][2] = s.Alo[m][p + 4];
                af[mt][3] = s.Alo[m + 8][p + 4];
            }
            #pragma unroll
            for (int mt = 0; mt < 4; ++mt)
                #pragma unroll
                for (int nt = 0; nt < 4; ++nt)
                    mma_bf16(acc[mt][nt], af[mt][0], af[mt][1], af[mt][2], af[mt][3],
                             bh[nt][0], bh[nt][1]);
        }
        __syncthreads();
    }

    #pragma unroll
    for (int mt = 0; mt < 4; ++mt) {
        int m = m0 + wm * 64 + mt * 16 + grp;
        #pragma unroll
        for (int nt = 0; nt < 4; ++nt) {
            int n = wn * 32 + nt * 8 + 2 * q;
            if (m < M)
                *(float2*)&C[(size_t)m * 128 + n] = make_float2(acc[mt][nt][0], acc[mt][nt][1]);
            if (m + 8 < M)
                *(float2*)&C[(size_t)(m + 8) * 128 + n] = make_float2(acc[mt][nt][2], acc[mt][nt][3]);
        }
    }
}

// ================= fused per-node pipeline: tensor-core version =================
#define XLD 132

struct SmemN {
    float E[32][XLD];
    float A[32][XLD];
    float B[32][XLD];
    float H[32][XLD];
    float red[32][8][2];
    float g[32];
};
#define NODE_SMEM_BYTES ((int)sizeof(SmemN))

__device__ __forceinline__ void zacc(float acc[2][2][4]) {
    #pragma unroll
    for (int i = 0; i < 2; ++i)
        #pragma unroll
        for (int j = 0; j < 2; ++j)
            #pragma unroll
            for (int k = 0; k < 4; ++k) acc[i][j][k] = 0.f;
}

__device__ __forceinline__ void npass1(const float (*__restrict__ X)[XLD],
                                       const float* __restrict__ W,
                                       float acc[2][2][4], int n0, int grp, int q) {
    #pragma unroll 4
    for (int kc = 0; kc < 16; ++kc) {
        int k0 = kc * 8;
        unsigned a[2][4];
        #pragma unroll
        for (int mt = 0; mt < 2; ++mt) {
            a[mt][0] = cvt_tf32(X[mt * 16 + grp    ][k0 + q]);
            a[mt][1] = cvt_tf32(X[mt * 16 + grp + 8][k0 + q]);
            a[mt][2] = cvt_tf32(X[mt * 16 + grp    ][k0 + q + 4]);
            a[mt][3] = cvt_tf32(X[mt * 16 + grp + 8][k0 + q + 4]);
        }
        unsigned b[2][2];
        #pragma unroll
        for (int nt = 0; nt < 2; ++nt) {
            b[nt][0] = cvt_tf32(__ldg(&W[(k0 + q)     * 128 + n0 + nt * 8 + grp]));
            b[nt][1] = cvt_tf32(__ldg(&W[(k0 + q + 4) * 128 + n0 + nt * 8 + grp]));
        }
        #pragma unroll
        for (int mt = 0; mt < 2; ++mt)
            #pragma unroll
            for (int nt = 0; nt < 2; ++nt)
                mma_tf32(acc[mt][nt], a[mt][0], a[mt][1], a[mt][2], a[mt][3],
                         b[nt][0], b[nt][1]);
    }
}

__device__ __forceinline__ void npass3(const float (*__restrict__ X)[XLD],
                                       const float* __restrict__ W,
                                       float acc[2][2][4], int n0, int grp, int q) {
    #pragma unroll 2
    for (int kc = 0; kc < 16; ++kc) {
        int k0 = kc * 8;
        unsigned ah[2][4], al[2][4];
        #pragma unroll
        for (int mt = 0; mt < 2; ++mt) {
            float x0 = X[mt * 16 + grp    ][k0 + q];
            float x1 = X[mt * 16 + grp + 8][k0 + q];
            float x2 = X[mt * 16 + grp    ][k0 + q + 4];
            float x3 = X[mt * 16 + grp + 8][k0 + q + 4];
            ah[mt][0] = cvt_tf32(x0); al[mt][0] = cvt_tf32(x0 - __uint_as_float(ah[mt][0]));
            ah[mt][1] = cvt_tf32(x1); al[mt][1] = cvt_tf32(x1 - __uint_as_float(ah[mt][1]));
            ah[mt][2] = cvt_tf32(x2); al[mt][2] = cvt_tf32(x2 - __uint_as_float(ah[mt][2]));
            ah[mt][3] = cvt_tf32(x3); al[mt][3] = cvt_tf32(x3 - __uint_as_float(ah[mt][3]));
        }
        unsigned bh[2][2], bl[2][2];
        #pragma unroll
        for (int nt = 0; nt < 2; ++nt) {
            float w0 = __ldg(&W[(k0 + q)     * 128 + n0 + nt * 8 + grp]);
            float w1 = __ldg(&W[(k0 + q + 4) * 128 + n0 + nt * 8 + grp]);
            bh[nt][0] = cvt_tf32(w0); bl[nt][0] = cvt_tf32(w0 - __uint_as_float(bh[nt][0]));
            bh[nt][1] = cvt_tf32(w1); bl[nt][1] = cvt_tf32(w1 - __uint_as_float(bh[nt][1]));
        }
        #pragma unroll
        for (int mt = 0; mt < 2; ++mt)
            #pragma unroll
            for (int nt = 0; nt < 2; ++nt) {
                mma_tf32(acc[mt][nt], ah[mt][0], ah[mt][1], ah[mt][2], ah[mt][3],
                         bh[nt][0], bh[nt][1]);
                mma_tf32(acc[mt][nt], ah[mt][0], ah[mt][1], ah[mt][2], ah[mt][3],
                         bl[nt][0], bl[nt][1]);
                mma_tf32(acc[mt][nt], al[mt][0], al[mt][1], al[mt][2], al[mt][3],
                         bh[nt][0], bh[nt][1]);
            }
    }
}

__device__ __forceinline__ void relu_store(SmemN& s, float acc[2][2][4],
                                           const float* __restrict__ bp,
                                           int n0, int grp, int q) {
    #pragma unroll
    for (int nt = 0; nt < 2; ++nt) {
        int col = n0 + nt * 8 + 2 * q;
        float2 b = __ldg((const float2*)&bp[col]);
        #pragma unroll
        for (int mt = 0; mt < 2; ++mt) {
            int r1 = mt * 16 + grp;
            s.H[r1][col]     = fmaxf(acc[mt][nt][0] + b.x, 0.f);
            s.H[r1][col + 1] = fmaxf(acc[mt][nt][1] + b.y, 0.f);
            s.H[r1 + 8][col]     = fmaxf(acc[mt][nt][2] + b.x, 0.f);
            s.H[r1 + 8][col + 1] = fmaxf(acc[mt][nt][3] + b.y, 0.f);
        }
    }
}

__device__ __forceinline__ void gate_finish(SmemN& s, float acc[2][2][4],
                                            const float* __restrict__ b2p,
                                            const float* __restrict__ w3p,
                                            const float* __restrict__ b3p,
                                            int n0, int grp, int q, int warp, int tid) {
    float part[4] = {0.f, 0.f, 0.f, 0.f};
    #pragma unroll
    for (int nt = 0; nt < 2; ++nt) {
        int col = n0 + nt * 8 + 2 * q;
        float2 b2 = __ldg((const float2*)&b2p[col]);
        float2 w3 = __ldg((const float2*)&w3p[col]);
        #pragma unroll
        for (int mt = 0; mt < 2; ++mt) {
            part[mt * 2 + 0] += fmaxf(acc[mt][nt][0] + b2.x, 0.f) * w3.x
                              + fmaxf(acc[mt][nt][1] + b2.y, 0.f) * w3.y;
            part[mt * 2 + 1] += fmaxf(acc[mt][nt][2] + b2.x, 0.f) * w3.x
                              + fmaxf(acc[mt][nt][3] + b2.y, 0.f) * w3.y;
        }
    }
    #pragma unroll
    for (int i = 0; i < 4; ++i) {
        part[i] += __shfl_xor_sync(0xffffffffu, part[i], 1);
        part[i] += __shfl_xor_sync(0xffffffffu, part[i], 2);
    }
    if (q == 0) {
        #pragma unroll
        for (int mt = 0; mt < 2; ++mt) {
            s.red[mt * 16 + grp][warp][0]     = part[mt * 2 + 0];
            s.red[mt * 16 + grp + 8][warp][0] = part[mt * 2 + 1];
        }
    }
    __syncthreads();
    if (tid < 32) {
        float v = 0.f;
        #pragma unroll
        for (int w = 0; w < 8; ++w) v += s.red[tid][w][0];
        s.g[tid] = 1.f / (1.f + expf(-(v + __ldg(b3p))));
    }
    __syncthreads();
}

__global__ __launch_bounds__(256, 3)
void k_node(const int* __restrict__ node_id, const float* __restrict__ emb,
            const float* __restrict__ iW1, const float* __restrict__ ib1,
            const float* __restrict__ iW2, const float* __restrict__ ib2,
            const float* __restrict__ iW3, const float* __restrict__ ib3,
            const float* __restrict__ tW1, const float* __restrict__ tb1,
            const float* __restrict__ tW2, const float* __restrict__ tb2,
            const float* __restrict__ tW3, const float* __restrict__ tb3,
            const float* __restrict__ cW,  const float* __restrict__ cb,
            const float* __restrict__ fW,  const float* __restrict__ attn_a,
            int N) {
    extern __shared__ char smem_raw[];
    SmemN& s = *reinterpret_cast<SmemN*>(smem_raw);
    int tid = threadIdx.x;
    int warp = tid >> 5, lane = tid & 31;
    int grp = lane >> 2, q = lane & 3;
    int n0 = warp * 16;
    int r8 = tid >> 5, c32 = tid & 31;
    int base = blockIdx.x * 32;

    #pragma unroll
    for (int it = 0; it < 4; ++it) {
        int idx = tid + it * 256;
        int n = idx >> 5, c4 = idx & 31;
        int gn = base + n;
        int nid = (gn < N) ? __ldg(&node_id[gn]) : 0;
        *(float4*)&s.E[n][c4 * 4] = *(const float4*)&emb[(size_t)nid * 128 + c4 * 4];
        float4 iv = make_float4(0.f, 0.f, 0.f, 0.f);
        float4 tv = make_float4(0.f, 0.f, 0.f, 0.f);
        if (gn < N) {
            iv = *(const float4*)&g_img_f[(size_t)gn * 128 + c4 * 4];
            tv = *(const float4*)&g_txt_f[(size_t)gn * 128 + c4 * 4];
        }
        *(float4*)&s.A[n][c4 * 4] = iv;
        *(float4*)&s.B[n][c4 * 4] = tv;
    }
    __syncthreads();

    float acc[2][2][4];

    zacc(acc);
    npass1(s.E, iW1, acc, n0, grp, q);
    npass1(s.A, iW1 + 128 * 128, acc, n0, grp, q);
    relu_store(s, acc, ib1, n0, grp, q);
    __syncthreads();

    zacc(acc);
    npass1(s.H, iW2, acc, n0, grp, q);
    gate_finish(s, acc, ib2, iW3, ib3, n0, grp, q, warp, tid);

    #pragma unroll
    for (int i = 0; i < 4; ++i) {
        float gv = s.g[r8 * 4 + i];
        float4 av = *(const float4*)&s.A[r8 * 4 + i][c32 * 4];
        float4 ev = *(const float4*)&s.E[r8 * 4 + i][c32 * 4];
        av.x = gv * av.x + (1.f - gv) * ev.x;
        av.y = gv * av.y + (1.f - gv) * ev.y;
        av.z = gv * av.z + (1.f - gv) * ev.z;
        av.w = gv * av.w + (1.f - gv) * ev.w;
        *(float4*)&s.A[r8 * 4 + i][c32 * 4] = av;
    }

    zacc(acc);
    npass1(s.E, tW1, acc, n0, grp, q);
    npass1(s.B, tW1 + 128 * 128, acc, n0, grp, q);
    relu_store(s, acc, tb1, n0, grp, q);
    __syncthreads();

    zacc(acc);
    npass1(s.H, tW2, acc, n0, grp, q);
    gate_finish(s, acc, tb2, tW3, tb3, n0, grp, q, warp, tid);

    #pragma unroll
    for (int i = 0; i < 4; ++i) {
        float gv = s.g[r8 * 4 + i];
        float4 bv = *(const float4*)&s.B[r8 * 4 + i][c32 * 4];
        float4 ev = *(const float4*)&s.E[r8 * 4 + i][c32 * 4];
        bv.x = gv * bv.x + (1.f - gv) * ev.x;
        bv.y = gv * bv.y + (1.f - gv) * ev.y;
        bv.z = gv * bv.z + (1.f - gv) * ev.z;
        bv.w = gv * bv.w + (1.f - gv) * ev.w;
        *(float4*)&s.B[r8 * 4 + i][c32 * 4] = bv;
    }
    __syncthreads();

    zacc(acc);
    npass3(s.A, cW, acc, n0, grp, q);
    npass3(s.B, cW + 128 * 128, acc, n0, grp, q);
    {
        #pragma unroll
        for (int nt = 0; nt < 2; ++nt) {
            int col = n0 + nt * 8 + 2 * q;
            float2 cbv = __ldg((const float2*)&cb[col]);
            #pragma unroll
            for (int mt = 0; mt < 2; ++mt) {
                int r1 = mt * 16 + grp, r2 = r1 + 8;
                float g0 = acc[mt][nt][0] + cbv.x;
                float g1 = acc[mt][nt][1] + cbv.y;
                float g2 = acc[mt][nt][2] + cbv.x;
                float g3 = acc[mt][nt][3] + cbv.y;
                float2 av1 = *(const float2*)&s.A[r1][col];
                float2 bv1 = *(const float2*)&s.B[r1][col];
                float2 av2 = *(const float2*)&s.A[r2][col];
                float2 bv2 = *(const float2*)&s.B[r2][col];
                s.H[r1][col]     = g0 * av1.x + (1.f - g0) * bv1.x;
                s.H[r1][col + 1] = g1 * av1.y + (1.f - g1) * bv1.y;
                s.H[r2][col]     = g2 * av2.x + (1.f - g2) * bv2.x;
                s.H[r2][col + 1] = g3 * av2.y + (1.f - g3) * bv2.y;
            }
        }
    }
    __syncthreads();

    zacc(acc);
    npass3(s.H, fW, acc, n0, grp, q);
    {
        float p1[4] = {0.f, 0.f, 0.f, 0.f};
        float p2[4] = {0.f, 0.f, 0.f, 0.f};
        #pragma unroll
        for (int nt = 0; nt < 2; ++nt) {
            int col = n0 + nt * 8 + 2 * q;
            float2 a1 = __ldg((const float2*)&attn_a[col]);
            float2 a2 = __ldg((const float2*)&attn_a[128 + col]);
            #pragma unroll
            for (int mt = 0; mt < 2; ++mt) {
                int r1 = mt * 16 + grp, r2 = r1 + 8;
                int g1_ = base + r1, g2_ = base + r2;
                if (g1_ < N)
                    *(float2*)&g_z[(size_t)g1_ * 128 + col] =
                        make_float2(acc[mt][nt][0], acc[mt][nt][1]);
                if (g2_ < N)
                    *(float2*)&g_z[(size_t)g2_ * 128 + col] =
                        make_float2(acc[mt][nt][2], acc[mt][nt][3]);
                p1[mt * 2 + 0] += acc[mt][nt][0] * a1.x + acc[mt][nt][1] * a1.y;
                p1[mt * 2 + 1] += acc[mt][nt][2] * a1.x + acc[mt][nt][3] * a1.y;
                p2[mt * 2 + 0] += acc[mt][nt][0] * a2.x + acc[mt][nt][1] * a2.y;
                p2[mt * 2 + 1] += acc[mt][nt][2] * a2.x + acc[mt][nt][3] * a2.y;
            }
        }
        #pragma unroll
        for (int i = 0; i < 4; ++i) {
            p1[i] += __shfl_xor_sync(0xffffffffu, p1[i], 1);
            p1[i] += __shfl_xor_sync(0xffffffffu, p1[i], 2);
            p2[i] += __shfl_xor_sync(0xffffffffu, p2[i], 1);
            p2[i] += __shfl_xor_sync(0xffffffffu, p2[i], 2);
        }
        if (q == 0) {
            #pragma unroll
            for (int mt = 0; mt < 2; ++mt) {
                s.red[mt * 16 + grp][warp][0]     = p1[mt * 2 + 0];
                s.red[mt * 16 + grp + 8][warp][0] = p1[mt * 2 + 1];
                s.red[mt * 16 + grp][warp][1]     = p2[mt * 2 + 0];
                s.red[mt * 16 + grp + 8][warp][1] = p2[mt * 2 + 1];
            }
        }
        __syncthreads();
        if (tid < 32) {
            float v1 = 0.f, v2 = 0.f;
            #pragma unroll
            for (int w = 0; w < 8; ++w) { v1 += s.red[tid][w][0]; v2 += s.red[tid][w][1]; }
            int gn = base + tid;
            if (gn < N) { g_esrc[gn] = v1; g_edst[gn] = v2; }
        }
    }
}

// ---------------- CSR aggregate: warp per dst node, no atomics ----------------
__global__ __launch_bounds__(256)
void k_agg(float* __restrict__ out, int N) {
    int w = (int)((blockIdx.x * (size_t)blockDim.x + threadIdx.x) >> 5);
    int lane = threadIdx.x & 31;
    if (w >= N) return;
    int beg = g_row[w], end = g_row[w + 1];
    float ed = g_edst[w];

    float m = -CUDART_INF_F;
    for (int i = beg + lane; i < end; i += 32) {
        float e = g_esrc[g_eidx[i]] + ed;
        e = (e >= 0.f) ? e : 0.01f * e;
        m = fmaxf(m, e);
    }
    #pragma unroll
    for (int off = 16; off > 0; off >>= 1)
        m = fmaxf(m, __shfl_xor_sync(0xffffffffu, m, off));

    float4 acc = make_float4(0.f, 0.f, 0.f, 0.f);
    float denom = 0.f;
    for (int basei = beg; basei < end; basei += 32) {
        int idx = basei + lane;
        float wgt = 0.f; int sj = 0;
        if (idx < end) {
            sj = g_eidx[idx];
            float e = g_esrc[sj] + ed;
            e = (e >= 0.f) ? e : 0.01f * e;
            wgt = expf(e - m);
        }
        int cnt = min(32, end - basei);
        for (int j = 0; j < cnt; ++j) {
            float wj = __shfl_sync(0xffffffffu, wgt, j);
            int   s_ = __shfl_sync(0xffffffffu, sj, j);
            float4 zv = __ldg((const float4*)&g_z[(size_t)s_ * 128 + lane * 4]);
            acc.x = fmaf(wj, zv.x, acc.x);
            acc.y = fmaf(wj, zv.y, acc.y);
            acc.z = fmaf(wj, zv.z, acc.z);
            acc.w = fmaf(wj, zv.w, acc.w);
            denom += wj;
        }
    }
    float inv = (denom > 1e-20f) ? 1.f / denom : 0.f;
    acc.x *= inv; acc.y *= inv; acc.z *= inv; acc.w *= inv;
    *(float4*)&out[(size_t)w * 128 + lane * 4] = acc;
}

// ---------------- launch ----------------
extern "C" void kernel_launch(void* const* d_in, const int* in_sizes, int n_in,
                              void* d_out, int out_size) {
    const int*   node_id = (const int*)  d_in[0];
    const float* img_h   = (const float*)d_in[1];
    const float* txt_h   = (const float*)d_in[2];
    const int*   src     = (const int*)  d_in[3];
    const int*   dst     = (const int*)  d_in[4];
    const float* emb     = (const float*)d_in[5];
    const float* W_img   = (const float*)d_in[6];
    const float* iW1     = (const float*)d_in[7];
    const float* ib1     = (const float*)d_in[8];
    const float* iW2     = (const float*)d_in[9];
    const float* ib2     = (const float*)d_in[10];
    const float* iW3     = (const float*)d_in[11];
    const float* ib3     = (const float*)d_in[12];
    const float* W_txt   = (const float*)d_in[13];
    const float* tW1     = (const float*)d_in[14];
    const float* tb1     = (const float*)d_in[15];
    const float* tW2     = (const float*)d_in[16];
    const float* tb2     = (const float*)d_in[17];
    const float* tW3     = (const float*)d_in[18];
    const float* tb3     = (const float*)d_in[19];
    const float* cW      = (const float*)d_in[20];
    const float* cb      = (const float*)d_in[21];
    const float* fW      = (const float*)d_in[22];
    const float* attn_a  = (const float*)d_in[23];

    int N = in_sizes[0];
    int E = in_sizes[3];
    int IMG_D = in_sizes[1] / N;
    int TXT_D = in_sizes[2] / N;
    float* out = (float*)d_out;

    float *p_img_f, *p_txt_f;
    cudaGetSymbolAddress((void**)&p_img_f, g_img_f);
    cudaGetSymbolAddress((void**)&p_txt_f, g_txt_f);

    cudaFuncSetAttribute(k_node, cudaFuncAttributeMaxDynamicSharedMemorySize, NODE_SMEM_BYTES);
    cudaFuncSetAttribute(k_mma_gemm, cudaFuncAttributeMaxDynamicSharedMemorySize, MMA_SMEM_BYTES);

    // CSR build + GEMM (gemm placed at launch index 3 -> ncu profiles it)
    k_zero<<<(N + 255) / 256, 256>>>(N);                        // 0
    k_count<<<(E + 255) / 256, 256>>>(dst, E);                  // 1
    k_scan<<<1, 1024>>>(N);                                     // 2
    dim3 ggrid((N + 127) / 128, 2);
    k_mma_gemm<<<ggrid, 256, MMA_SMEM_BYTES>>>(img_h, txt_h, W_img, W_txt,
                                               p_img_f, p_txt_f, N, IMG_D, TXT_D); // 3
    k_scatter<<<(E + 255) / 256, 256>>>(src, dst, E);           // 4

    k_node<<<(N + 31) / 32, 256, NODE_SMEM_BYTES>>>(            // 5
        node_id, emb,
        iW1, ib1, iW2, ib2, iW3, ib3,
        tW1, tb1, tW2, tb2, tW3, tb3,
        cW, cb, fW, attn_a, N);

    k_agg<<<(N * 32 + 255) / 256, 256>>>(out, N);               // 6
}

// round 7
// speedup vs baseline: 1.4018x; 1.0349x over previous
#include <cuda_runtime.h>
#include <math_constants.h>
#include <cuda_bf16.h>

#define NN 50000
#define NE 800000
#define HID 128

// ---------------- scratch ----------------
__device__ float g_img_f[NN * HID];
__device__ float g_txt_f[NN * HID];
__device__ float g_z[NN * HID];
__device__ float g_esrc[NN];
__device__ float g_edst[NN];
__device__ int   g_cnt[NN];
__device__ int   g_fill[NN];
__device__ int   g_row[NN + 1];
__device__ int   g_eidx[NE];

// ---------------- CSR build ----------------
__global__ void k_zero(int n) {
    int i = blockIdx.x * blockDim.x + threadIdx.x;
    if (i < n) { g_cnt[i] = 0; g_fill[i] = 0; }
}

__global__ void k_count(const int* __restrict__ dst, int E) {
    int i = blockIdx.x * blockDim.x + threadIdx.x;
    if (i < E) atomicAdd(&g_cnt[dst[i]], 1);
}

__global__ __launch_bounds__(1024)
void k_scan(int n) {
    __shared__ int sh[1024];
    __shared__ int carry;
    int tid = threadIdx.x;
    if (tid == 0) carry = 0;
    __syncthreads();
    for (int base = 0; base < n; base += 1024) {
        int i = base + tid;
        int v = (i < n) ? g_cnt[i] : 0;
        sh[tid] = v;
        __syncthreads();
        #pragma unroll
        for (int off = 1; off < 1024; off <<= 1) {
            int t = (tid >= off) ? sh[tid - off] : 0;
            __syncthreads();
            sh[tid] += t;
            __syncthreads();
        }
        if (i < n) g_row[i] = sh[tid] - v + carry;   // exclusive
        int total = sh[1023];
        __syncthreads();
        if (tid == 0) carry += total;
        __syncthreads();
    }
    if (tid == 0) g_row[n] = carry;
}

__global__ void k_scatter(const int* __restrict__ src, const int* __restrict__ dst, int E) {
    int i = blockIdx.x * blockDim.x + threadIdx.x;
    if (i >= E) return;
    int d = dst[i];
    int pos = g_row[d] + atomicAdd(&g_fill[d], 1);
    g_eidx[pos] = src[i];
}

// ---------------- mma helpers ----------------
__device__ __forceinline__ unsigned cvt_tf32(float x) {
    unsigned r; asm("cvt.rna.tf32.f32 %0, %1;" : "=r"(r) : "f"(x)); return r;
}
__device__ __forceinline__ void mma_tf32(float c[4], unsigned a0, unsigned a1,
                                         unsigned a2, unsigned a3,
                                         unsigned b0, unsigned b1) {
    asm volatile(
        "mma.sync.aligned.m16n8k8.row.col.f32.tf32.tf32.f32 "
        "{%0,%1,%2,%3}, {%4,%5,%6,%7}, {%8,%9}, {%0,%1,%2,%3};"
        : "+f"(c[0]), "+f"(c[1]), "+f"(c[2]), "+f"(c[3])
        : "r"(a0), "r"(a1), "r"(a2), "r"(a3), "r"(b0), "r"(b1));
}
// pack two floats into bf16x2: lo-half = first arg, hi-half = second
__device__ __forceinline__ unsigned pkbf2(float lo, float hi) {
    unsigned r; asm("cvt.rn.bf16x2.f32 %0, %1, %2;" : "=r"(r) : "f"(hi), "f"(lo));
    return r;
}
__device__ __forceinline__ void mma_bf16(float c[4], unsigned a0, unsigned a1,
                                         unsigned a2, unsigned a3,
                                         unsigned b0, unsigned b1) {
    asm volatile(
        "mma.sync.aligned.m16n8k16.row.col.f32.bf16.bf16.f32 "
        "{%0,%1,%2,%3}, {%4,%5,%6,%7}, {%8,%9}, {%0,%1,%2,%3};"
        : "+f"(c[0]), "+f"(c[1]), "+f"(c[2]), "+f"(c[3])
        : "r"(a0), "r"(a1), "r"(a2), "r"(a3), "r"(b0), "r"(b1));
}

// ================= big input GEMMs: split-bf16, double-buffered pipeline =================
// BK=32 floats = 16 bf16-pairs per tile, two smem stage buffers, register prefetch.
#define APLD 20
#define BPLD 136

struct MmaSmem {
    unsigned Ahi[2][128][APLD];
    unsigned Alo[2][128][APLD];
    unsigned Bhi[2][16][BPLD];
    unsigned Blo[2][16][BPLD];
};
#define MMA_SMEM_BYTES ((int)sizeof(MmaSmem))

__global__ __launch_bounds__(256, 1)
void k_mma_gemm(const float* __restrict__ Ai, const float* __restrict__ At,
                const float* __restrict__ Bi, const float* __restrict__ Bt,
                float* __restrict__ Ci, float* __restrict__ Ct,
                int M, int Ki, int Kt) {
    extern __shared__ char smem_raw[];
    MmaSmem& s = *reinterpret_cast<MmaSmem*>(smem_raw);
    int sel = blockIdx.y;
    const float* A = sel ? At : Ai;
    const float* B = sel ? Bt : Bi;
    float*       C = sel ? Ct : Ci;
    int K = sel ? Kt : Ki;
    int ntile = K >> 5;

    int tid  = threadIdx.x;
    int warp = tid >> 5, lane = tid & 31;
    int wm = warp & 1;          // 64-row slab
    int wn = warp >> 1;         // 32-col slab
    int grp = lane >> 2, q = lane & 3;
    int m0 = blockIdx.x * 128;

    // per-thread staging coordinates
    int ar[4], ac4[4];
    #pragma unroll
    for (int i = 0; i < 4; ++i) { int f4 = tid + i * 256; ar[i] = f4 >> 3; ac4[i] = f4 & 7; }
    int bkp[8], bc[8];
    #pragma unroll
    for (int i = 0; i < 8; ++i) { int idx = tid + i * 256; bkp[i] = idx >> 7; bc[i] = idx & 127; }

    float4 apf[4];
    float2 bpf[8];

    auto load_tile = [&](int k0) {
        #pragma unroll
        for (int i = 0; i < 4; ++i) {
            apf[i] = make_float4(0.f, 0.f, 0.f, 0.f);
            if (m0 + ar[i] < M)
                apf[i] = *(const float4*)&A[(size_t)(m0 + ar[i]) * K + k0 + ac4[i] * 4];
        }
        #pragma unroll
        for (int i = 0; i < 8; ++i) {
            bpf[i].x = B[(size_t)(k0 + 2 * bkp[i])     * 128 + bc[i]];
            bpf[i].y = B[(size_t)(k0 + 2 * bkp[i] + 1) * 128 + bc[i]];
        }
    };

    auto store_tile = [&](int buf) {
        #pragma unroll
        for (int i = 0; i < 4; ++i) {
            unsigned h0 = pkbf2(apf[i].x, apf[i].y);
            unsigned h1 = pkbf2(apf[i].z, apf[i].w);
            float hx = __uint_as_float(h0 << 16);
            float hy = __uint_as_float(h0 & 0xffff0000u);
            float hz = __uint_as_float(h1 << 16);
            float hw = __uint_as_float(h1 & 0xffff0000u);
            *(uint2*)&s.Ahi[buf][ar[i]][2 * ac4[i]] = make_uint2(h0, h1);
            *(uint2*)&s.Alo[buf][ar[i]][2 * ac4[i]] =
                make_uint2(pkbf2(apf[i].x - hx, apf[i].y - hy),
                           pkbf2(apf[i].z - hz, apf[i].w - hw));
        }
        #pragma unroll
        for (int i = 0; i < 8; ++i) {
            unsigned h = pkbf2(bpf[i].x, bpf[i].y);
            float f0 = __uint_as_float(h << 16);
            float f1 = __uint_as_float(h & 0xffff0000u);
            s.Bhi[buf][bkp[i]][bc[i]] = h;
            s.Blo[buf][bkp[i]][bc[i]] = pkbf2(bpf[i].x - f0, bpf[i].y - f1);
        }
    };

    float acc[4][4][4];
    #pragma unroll
    for (int i = 0; i < 4; ++i)
        #pragma unroll
        for (int j = 0; j < 4; ++j)
            #pragma unroll
            for (int k = 0; k < 4; ++k) acc[i][j][k] = 0.f;

    // prologue
    load_tile(0);
    store_tile(0);
    __syncthreads();

    #pragma unroll 1
    for (int t = 0; t < ntile; ++t) {
        int buf = t & 1;
        if (t + 1 < ntile) load_tile((t + 1) * 32);   // LDGs in flight during MMA

        #pragma unroll
        for (int sstep = 0; sstep < 2; ++sstep) {
            int p = sstep * 8 + q;
            unsigned af[4][4], bh[4][2], bl[4][2];
            #pragma unroll
            for (int mt = 0; mt < 4; ++mt) {
                int m = wm * 64 + mt * 16 + grp;
                af[mt][0] = s.Ahi[buf][m][p];
                af[mt][1] = s.Ahi[buf][m + 8][p];
                af[mt][2] = s.Ahi[buf][m][p + 4];
                af[mt][3] = s.Ahi[buf][m + 8][p + 4];
            }
            #pragma unroll
            for (int nt = 0; nt < 4; ++nt) {
                int n = wn * 32 + nt * 8 + grp;
                bh[nt][0] = s.Bhi[buf][p][n];      bh[nt][1] = s.Bhi[buf][p + 4][n];
                bl[nt][0] = s.Blo[buf][p][n];      bl[nt][1] = s.Blo[buf][p + 4][n];
            }
            // hh + hl
            #pragma unroll
            for (int mt = 0; mt < 4; ++mt)
                #pragma unroll
                for (int nt = 0; nt < 4; ++nt) {
                    mma_bf16(acc[mt][nt], af[mt][0], af[mt][1], af[mt][2], af[mt][3],
                             bh[nt][0], bh[nt][1]);
                    mma_bf16(acc[mt][nt], af[mt][0], af[mt][1], af[mt][2], af[mt][3],
                             bl[nt][0], bl[nt][1]);
                }
            // lh
            #pragma unroll
            for (int mt = 0; mt < 4; ++mt) {
                int m = wm * 64 + mt * 16 + grp;
                af[mt][0] = s.Alo[buf][m][p];
                af[mt][1] = s.Alo[buf][m + 8][p];
                af[mt][2] = s.Alo[buf][m][p + 4];
                af[mt][3] = s.Alo[buf][m + 8][p + 4];
            }
            #pragma unroll
            for (int mt = 0; mt < 4; ++mt)
                #pragma unroll
                for (int nt = 0; nt < 4; ++nt)
                    mma_bf16(acc[mt][nt], af[mt][0], af[mt][1], af[mt][2], af[mt][3],
                             bh[nt][0], bh[nt][1]);
        }

        if (t + 1 < ntile) store_tile((t + 1) & 1);
        __syncthreads();
    }

    #pragma unroll
    for (int mt = 0; mt < 4; ++mt) {
        int m = m0 + wm * 64 + mt * 16 + grp;
        #pragma unroll
        for (int nt = 0; nt < 4; ++nt) {
            int n = wn * 32 + nt * 8 + 2 * q;
            if (m < M)
                *(float2*)&C[(size_t)m * 128 + n] = make_float2(acc[mt][nt][0], acc[mt][nt][1]);
            if (m + 8 < M)
                *(float2*)&C[(size_t)(m + 8) * 128 + n] = make_float2(acc[mt][nt][2], acc[mt][nt][3]);
        }
    }
}

// ================= fused per-node pipeline: tensor-core version =================
#define XLD 132

struct SmemN {
    float E[32][XLD];
    float A[32][XLD];
    float B[32][XLD];
    float H[32][XLD];
    float red[32][8][2];
    float g[32];
};
#define NODE_SMEM_BYTES ((int)sizeof(SmemN))

__device__ __forceinline__ void zacc(float acc[2][2][4]) {
    #pragma unroll
    for (int i = 0; i < 2; ++i)
        #pragma unroll
        for (int j = 0; j < 2; ++j)
            #pragma unroll
            for (int k = 0; k < 4; ++k) acc[i][j][k] = 0.f;
}

__device__ __forceinline__ void npass1(const float (*__restrict__ X)[XLD],
                                       const float* __restrict__ W,
                                       float acc[2][2][4], int n0, int grp, int q) {
    #pragma unroll 4
    for (int kc = 0; kc < 16; ++kc) {
        int k0 = kc * 8;
        unsigned a[2][4];
        #pragma unroll
        for (int mt = 0; mt < 2; ++mt) {
            a[mt][0] = cvt_tf32(X[mt * 16 + grp    ][k0 + q]);
            a[mt][1] = cvt_tf32(X[mt * 16 + grp + 8][k0 + q]);
            a[mt][2] = cvt_tf32(X[mt * 16 + grp    ][k0 + q + 4]);
            a[mt][3] = cvt_tf32(X[mt * 16 + grp + 8][k0 + q + 4]);
        }
        unsigned b[2][2];
        #pragma unroll
        for (int nt = 0; nt < 2; ++nt) {
            b[nt][0] = cvt_tf32(__ldg(&W[(k0 + q)     * 128 + n0 + nt * 8 + grp]));
            b[nt][1] = cvt_tf32(__ldg(&W[(k0 + q + 4) * 128 + n0 + nt * 8 + grp]));
        }
        #pragma unroll
        for (int mt = 0; mt < 2; ++mt)
            #pragma unroll
            for (int nt = 0; nt < 2; ++nt)
                mma_tf32(acc[mt][nt], a[mt][0], a[mt][1], a[mt][2], a[mt][3],
                         b[nt][0], b[nt][1]);
    }
}

__device__ __forceinline__ void npass3(const float (*__restrict__ X)[XLD],
                                       const float* __restrict__ W,
                                       float acc[2][2][4], int n0, int grp, int q) {
    #pragma unroll 2
    for (int kc = 0; kc < 16; ++kc) {
        int k0 = kc * 8;
        unsigned ah[2][4], al[2][4];
        #pragma unroll
        for (int mt = 0; mt < 2; ++mt) {
            float x0 = X[mt * 16 + grp    ][k0 + q];
            float x1 = X[mt * 16 + grp + 8][k0 + q];
            float x2 = X[mt * 16 + grp    ][k0 + q + 4];
            float x3 = X[mt * 16 + grp + 8][k0 + q + 4];
            ah[mt][0] = cvt_tf32(x0); al[mt][0] = cvt_tf32(x0 - __uint_as_float(ah[mt][0]));
            ah[mt][1] = cvt_tf32(x1); al[mt][1] = cvt_tf32(x1 - __uint_as_float(ah[mt][1]));
            ah[mt][2] = cvt_tf32(x2); al[mt][2] = cvt_tf32(x2 - __uint_as_float(ah[mt][2]));
            ah[mt][3] = cvt_tf32(x3); al[mt][3] = cvt_tf32(x3 - __uint_as_float(ah[mt][3]));
        }
        unsigned bh[2][2], bl[2][2];
        #pragma unroll
        for (int nt = 0; nt < 2; ++nt) {
            float w0 = __ldg(&W[(k0 + q)     * 128 + n0 + nt * 8 + grp]);
            float w1 = __ldg(&W[(k0 + q + 4) * 128 + n0 + nt * 8 + grp]);
            bh[nt][0] = cvt_tf32(w0); bl[nt][0] = cvt_tf32(w0 - __uint_as_float(bh[nt][0]));
            bh[nt][1] = cvt_tf32(w1); bl[nt][1] = cvt_tf32(w1 - __uint_as_float(bh[nt][1]));
        }
        #pragma unroll
        for (int mt = 0; mt < 2; ++mt)
            #pragma unroll
            for (int nt = 0; nt < 2; ++nt) {
                mma_tf32(acc[mt][nt], ah[mt][0], ah[mt][1], ah[mt][2], ah[mt][3],
                         bh[nt][0], bh[nt][1]);
                mma_tf32(acc[mt][nt], ah[mt][0], ah[mt][1], ah[mt][2], ah[mt][3],
                         bl[nt][0], bl[nt][1]);
                mma_tf32(acc[mt][nt], al[mt][0], al[mt][1], al[mt][2], al[mt][3],
                         bh[nt][0], bh[nt][1]);
            }
    }
}

__device__ __forceinline__ void relu_store(SmemN& s, float acc[2][2][4],
                                           const float* __restrict__ bp,
                                           int n0, int grp, int q) {
    #pragma unroll
    for (int nt = 0; nt < 2; ++nt) {
        int col = n0 + nt * 8 + 2 * q;
        float2 b = __ldg((const float2*)&bp[col]);
        #pragma unroll
        for (int mt = 0; mt < 2; ++mt) {
            int r1 = mt * 16 + grp;
            s.H[r1][col]     = fmaxf(acc[mt][nt][0] + b.x, 0.f);
            s.H[r1][col + 1] = fmaxf(acc[mt][nt][1] + b.y, 0.f);
            s.H[r1 + 8][col]     = fmaxf(acc[mt][nt][2] + b.x, 0.f);
            s.H[r1 + 8][col + 1] = fmaxf(acc[mt][nt][3] + b.y, 0.f);
        }
    }
}

__device__ __forceinline__ void gate_finish(SmemN& s, float acc[2][2][4],
                                            const float* __restrict__ b2p,
                                            const float* __restrict__ w3p,
                                            const float* __restrict__ b3p,
                                            int n0, int grp, int q, int warp, int tid) {
    float part[4] = {0.f, 0.f, 0.f, 0.f};
    #pragma unroll
    for (int nt = 0; nt < 2; ++nt) {
        int col = n0 + nt * 8 + 2 * q;
        float2 b2 = __ldg((const float2*)&b2p[col]);
        float2 w3 = __ldg((const float2*)&w3p[col]);
        #pragma unroll
        for (int mt = 0; mt < 2; ++mt) {
            part[mt * 2 + 0] += fmaxf(acc[mt][nt][0] + b2.x, 0.f) * w3.x
                              + fmaxf(acc[mt][nt][1] + b2.y, 0.f) * w3.y;
            part[mt * 2 + 1] += fmaxf(acc[mt][nt][2] + b2.x, 0.f) * w3.x
                              + fmaxf(acc[mt][nt][3] + b2.y, 0.f) * w3.y;
        }
    }
    #pragma unroll
    for (int i = 0; i < 4; ++i) {
        part[i] += __shfl_xor_sync(0xffffffffu, part[i], 1);
        part[i] += __shfl_xor_sync(0xffffffffu, part[i], 2);
    }
    if (q == 0) {
        #pragma unroll
        for (int mt = 0; mt < 2; ++mt) {
            s.red[mt * 16 + grp][warp][0]     = part[mt * 2 + 0];
            s.red[mt * 16 + grp + 8][warp][0] = part[mt * 2 + 1];
        }
    }
    __syncthreads();
    if (tid < 32) {
        float v = 0.f;
        #pragma unroll
        for (int w = 0; w < 8; ++w) v += s.red[tid][w][0];
        s.g[tid] = 1.f / (1.f + expf(-(v + __ldg(b3p))));
    }
    __syncthreads();
}

__global__ __launch_bounds__(256, 3)
void k_node(const int* __restrict__ node_id, const float* __restrict__ emb,
            const float* __restrict__ iW1, const float* __restrict__ ib1,
            const float* __restrict__ iW2, const float* __restrict__ ib2,
            const float* __restrict__ iW3, const float* __restrict__ ib3,
            const float* __restrict__ tW1, const float* __restrict__ tb1,
            const float* __restrict__ tW2, const float* __restrict__ tb2,
            const float* __restrict__ tW3, const float* __restrict__ tb3,
            const float* __restrict__ cW,  const float* __restrict__ cb,
            const float* __restrict__ fW,  const float* __restrict__ attn_a,
            int N) {
    extern __shared__ char smem_raw[];
    SmemN& s = *reinterpret_cast<SmemN*>(smem_raw);
    int tid = threadIdx.x;
    int warp = tid >> 5, lane = tid & 31;
    int grp = lane >> 2, q = lane & 3;
    int n0 = warp * 16;
    int r8 = tid >> 5, c32 = tid & 31;
    int base = blockIdx.x * 32;

    #pragma unroll
    for (int it = 0; it < 4; ++it) {
        int idx = tid + it * 256;
        int n = idx >> 5, c4 = idx & 31;
        int gn = base + n;
        int nid = (gn < N) ? __ldg(&node_id[gn]) : 0;
        *(float4*)&s.E[n][c4 * 4] = *(const float4*)&emb[(size_t)nid * 128 + c4 * 4];
        float4 iv = make_float4(0.f, 0.f, 0.f, 0.f);
        float4 tv = make_float4(0.f, 0.f, 0.f, 0.f);
        if (gn < N) {
            iv = *(const float4*)&g_img_f[(size_t)gn * 128 + c4 * 4];
            tv = *(const float4*)&g_txt_f[(size_t)gn * 128 + c4 * 4];
        }
        *(float4*)&s.A[n][c4 * 4] = iv;
        *(float4*)&s.B[n][c4 * 4] = tv;
    }
    __syncthreads();

    float acc[2][2][4];

    zacc(acc);
    npass1(s.E, iW1, acc, n0, grp, q);
    npass1(s.A, iW1 + 128 * 128, acc, n0, grp, q);
    relu_store(s, acc, ib1, n0, grp, q);
    __syncthreads();

    zacc(acc);
    npass1(s.H, iW2, acc, n0, grp, q);
    gate_finish(s, acc, ib2, iW3, ib3, n0, grp, q, warp, tid);

    #pragma unroll
    for (int i = 0; i < 4; ++i) {
        float gv = s.g[r8 * 4 + i];
        float4 av = *(const float4*)&s.A[r8 * 4 + i][c32 * 4];
        float4 ev = *(const float4*)&s.E[r8 * 4 + i][c32 * 4];
        av.x = gv * av.x + (1.f - gv) * ev.x;
        av.y = gv * av.y + (1.f - gv) * ev.y;
        av.z = gv * av.z + (1.f - gv) * ev.z;
        av.w = gv * av.w + (1.f - gv) * ev.w;
        *(float4*)&s.A[r8 * 4 + i][c32 * 4] = av;
    }

    zacc(acc);
    npass1(s.E, tW1, acc, n0, grp, q);
    npass1(s.B, tW1 + 128 * 128, acc, n0, grp, q);
    relu_store(s, acc, tb1, n0, grp, q);
    __syncthreads();

    zacc(acc);
    npass1(s.H, tW2, acc, n0, grp, q);
    gate_finish(s, acc, tb2, tW3, tb3, n0, grp, q, warp, tid);

    #pragma unroll
    for (int i = 0; i < 4; ++i) {
        float gv = s.g[r8 * 4 + i];
        float4 bv = *(const float4*)&s.B[r8 * 4 + i][c32 * 4];
        float4 ev = *(const float4*)&s.E[r8 * 4 + i][c32 * 4];
        bv.x = gv * bv.x + (1.f - gv) * ev.x;
        bv.y = gv * bv.y + (1.f - gv) * ev.y;
        bv.z = gv * bv.z + (1.f - gv) * ev.z;
        bv.w = gv * bv.w + (1.f - gv) * ev.w;
        *(float4*)&s.B[r8 * 4 + i][c32 * 4] = bv;
    }
    __syncthreads();

    zacc(acc);
    npass3(s.A, cW, acc, n0, grp, q);
    npass3(s.B, cW + 128 * 128, acc, n0, grp, q);
    {
        #pragma unroll
        for (int nt = 0; nt < 2; ++nt) {
            int col = n0 + nt * 8 + 2 * q;
            float2 cbv = __ldg((const float2*)&cb[col]);
            #pragma unroll
            for (int mt = 0; mt < 2; ++mt) {
                int r1 = mt * 16 + grp, r2 = r1 + 8;
                float g0 = acc[mt][nt][0] + cbv.x;
                float g1 = acc[mt][nt][1] + cbv.y;
                float g2 = acc[mt][nt][2] + cbv.x;
                float g3 = acc[mt][nt][3] + cbv.y;
                float2 av1 = *(const float2*)&s.A[r1][col];
                float2 bv1 = *(const float2*)&s.B[r1][col];
                float2 av2 = *(const float2*)&s.A[r2][col];
                float2 bv2 = *(const float2*)&s.B[r2][col];
                s.H[r1][col]     = g0 * av1.x + (1.f - g0) * bv1.x;
                s.H[r1][col + 1] = g1 * av1.y + (1.f - g1) * bv1.y;
                s.H[r2][col]     = g2 * av2.x + (1.f - g2) * bv2.x;
                s.H[r2][col + 1] = g3 * av2.y + (1.f - g3) * bv2.y;
            }
        }
    }
    __syncthreads();

    zacc(acc);
    npass3(s.H, fW, acc, n0, grp, q);
    {
        float p1[4] = {0.f, 0.f, 0.f, 0.f};
        float p2[4] = {0.f, 0.f, 0.f, 0.f};
        #pragma unroll
        for (int nt = 0; nt < 2; ++nt) {
            int col = n0 + nt * 8 + 2 * q;
            float2 a1 = __ldg((const float2*)&attn_a[col]);
            float2 a2 = __ldg((const float2*)&attn_a[128 + col]);
            #pragma unroll
            for (int mt = 0; mt < 2; ++mt) {
                int r1 = mt * 16 + grp, r2 = r1 + 8;
                int g1_ = base + r1, g2_ = base + r2;
                if (g1_ < N)
                    *(float2*)&g_z[(size_t)g1_ * 128 + col] =
                        make_float2(acc[mt][nt][0], acc[mt][nt][1]);
                if (g2_ < N)
                    *(float2*)&g_z[(size_t)g2_ * 128 + col] =
                        make_float2(acc[mt][nt][2], acc[mt][nt][3]);
                p1[mt * 2 + 0] += acc[mt][nt][0] * a1.x + acc[mt][nt][1] * a1.y;
                p1[mt * 2 + 1] += acc[mt][nt][2] * a1.x + acc[mt][nt][3] * a1.y;
                p2[mt * 2 + 0] += acc[mt][nt][0] * a2.x + acc[mt][nt][1] * a2.y;
                p2[mt * 2 + 1] += acc[mt][nt][2] * a2.x + acc[mt][nt][3] * a2.y;
            }
        }
        #pragma unroll
        for (int i = 0; i < 4; ++i) {
            p1[i] += __shfl_xor_sync(0xffffffffu, p1[i], 1);
            p1[i] += __shfl_xor_sync(0xffffffffu, p1[i], 2);
            p2[i] += __shfl_xor_sync(0xffffffffu, p2[i], 1);
            p2[i] += __shfl_xor_sync(0xffffffffu, p2[i], 2);
        }
        if (q == 0) {
            #pragma unroll
            for (int mt = 0; mt < 2; ++mt) {
                s.red[mt * 16 + grp][warp][0]     = p1[mt * 2 + 0];
                s.red[mt * 16 + grp + 8][warp][0] = p1[mt * 2 + 1];
                s.red[mt * 16 + grp][warp][1]     = p2[mt * 2 + 0];
                s.red[mt * 16 + grp + 8][warp][1] = p2[mt * 2 + 1];
            }
        }
        __syncthreads();
        if (tid < 32) {
            float v1 = 0.f, v2 = 0.f;
            #pragma unroll
            for (int w = 0; w < 8; ++w) { v1 += s.red[tid][w][0]; v2 += s.red[tid][w][1]; }
            int gn = base + tid;
            if (gn < N) { g_esrc[gn] = v1; g_edst[gn] = v2; }
        }
    }
}

// ---------------- CSR aggregate: warp per dst node, no atomics ----------------
__global__ __launch_bounds__(256)
void k_agg(float* __restrict__ out, int N) {
    int w = (int)((blockIdx.x * (size_t)blockDim.x + threadIdx.x) >> 5);
    int lane = threadIdx.x & 31;
    if (w >= N) return;
    int beg = g_row[w], end = g_row[w + 1];
    float ed = g_edst[w];

    float m = -CUDART_INF_F;
    for (int i = beg + lane; i < end; i += 32) {
        float e = g_esrc[g_eidx[i]] + ed;
        e = (e >= 0.f) ? e : 0.01f * e;
        m = fmaxf(m, e);
    }
    #pragma unroll
    for (int off = 16; off > 0; off >>= 1)
        m = fmaxf(m, __shfl_xor_sync(0xffffffffu, m, off));

    float4 acc = make_float4(0.f, 0.f, 0.f, 0.f);
    float denom = 0.f;
    for (int basei = beg; basei < end; basei += 32) {
        int idx = basei + lane;
        float wgt = 0.f; int sj = 0;
        if (idx < end) {
            sj = g_eidx[idx];
            float e = g_esrc[sj] + ed;
            e = (e >= 0.f) ? e : 0.01f * e;
            wgt = expf(e - m);
        }
        int cnt = min(32, end - basei);
        for (int j = 0; j < cnt; ++j) {
            float wj = __shfl_sync(0xffffffffu, wgt, j);
            int   s_ = __shfl_sync(0xffffffffu, sj, j);
            float4 zv = __ldg((const float4*)&g_z[(size_t)s_ * 128 + lane * 4]);
            acc.x = fmaf(wj, zv.x, acc.x);
            acc.y = fmaf(wj, zv.y, acc.y);
            acc.z = fmaf(wj, zv.z, acc.z);
            acc.w = fmaf(wj, zv.w, acc.w);
            denom += wj;
        }
    }
    float inv = (denom > 1e-20f) ? 1.f / denom : 0.f;
    acc.x *= inv; acc.y *= inv; acc.z *= inv; acc.w *= inv;
    *(float4*)&out[(size_t)w * 128 + lane * 4] = acc;
}

// ---------------- launch ----------------
extern "C" void kernel_launch(void* const* d_in, const int* in_sizes, int n_in,
                              void* d_out, int out_size) {
    const int*   node_id = (const int*)  d_in[0];
    const float* img_h   = (const float*)d_in[1];
    const float* txt_h   = (const float*)d_in[2];
    const int*   src     = (const int*)  d_in[3];
    const int*   dst     = (const int*)  d_in[4];
    const float* emb     = (const float*)d_in[5];
    const float* W_img   = (const float*)d_in[6];
    const float* iW1     = (const float*)d_in[7];
    const float* ib1     = (const float*)d_in[8];
    const float* iW2     = (const float*)d_in[9];
    const float* ib2     = (const float*)d_in[10];
    const float* iW3     = (const float*)d_in[11];
    const float* ib3     = (const float*)d_in[12];
    const float* W_txt   = (const float*)d_in[13];
    const float* tW1     = (const float*)d_in[14];
    const float* tb1     = (const float*)d_in[15];
    const float* tW2     = (const float*)d_in[16];
    const float* tb2     = (const float*)d_in[17];
    const float* tW3     = (const float*)d_in[18];
    const float* tb3     = (const float*)d_in[19];
    const float* cW      = (const float*)d_in[20];
    const float* cb      = (const float*)d_in[21];
    const float* fW      = (const float*)d_in[22];
    const float* attn_a  = (const float*)d_in[23];

    int N = in_sizes[0];
    int E = in_sizes[3];
    int IMG_D = in_sizes[1] / N;
    int TXT_D = in_sizes[2] / N;
    float* out = (float*)d_out;

    float *p_img_f, *p_txt_f;
    cudaGetSymbolAddress((void**)&p_img_f, g_img_f);
    cudaGetSymbolAddress((void**)&p_txt_f, g_txt_f);

    cudaFuncSetAttribute(k_node, cudaFuncAttributeMaxDynamicSharedMemorySize, NODE_SMEM_BYTES);
    cudaFuncSetAttribute(k_mma_gemm, cudaFuncAttributeMaxDynamicSharedMemorySize, MMA_SMEM_BYTES);

    // launch order puts k_node at index 3 (ncu captures index 3)
    k_zero<<<(N + 255) / 256, 256>>>(N);                        // 0
    k_count<<<(E + 255) / 256, 256>>>(dst, E);                  // 1
    dim3 ggrid((N + 127) / 128, 2);
    k_mma_gemm<<<ggrid, 256, MMA_SMEM_BYTES>>>(img_h, txt_h, W_img, W_txt,
                                               p_img_f, p_txt_f, N, IMG_D, TXT_D); // 2
    k_node<<<(N + 31) / 32, 256, NODE_SMEM_BYTES>>>(            // 3
        node_id, emb,
        iW1, ib1, iW2, ib2, iW3, ib3,
        tW1, tb1, tW2, tb2, tW3, tb3,
        cW, cb, fW, attn_a, N);
    k_scan<<<1, 1024>>>(N);                                     // 4
    k_scatter<<<(E + 255) / 256, 256>>>(src, dst, E);           // 5
    k_agg<<<(N * 32 + 255) / 256, 256>>>(out, N);               // 6
}

// round 8
// speedup vs baseline: 1.4803x; 1.0560x over previous
#include <cuda_runtime.h>
#include <math_constants.h>
#include <cuda_bf16.h>

#define NN 50000
#define NE 800000
#define HID 128

// ---------------- scratch ----------------
__device__ float g_img_f[NN * HID];
__device__ float g_txt_f[NN * HID];
__device__ float g_z[NN * HID];
__device__ float g_esrc[NN];
__device__ float g_edst[NN];
__device__ int   g_cnt[NN];
__device__ int   g_fill[NN];
__device__ int   g_row[NN + 1];
__device__ int   g_eidx[NE];

// ---------------- CSR build ----------------
__global__ void k_zero(int n) {
    int i = blockIdx.x * blockDim.x + threadIdx.x;
    if (i < n) { g_cnt[i] = 0; g_fill[i] = 0; }
}

__global__ void k_count(const int* __restrict__ dst, int E) {
    int i = blockIdx.x * blockDim.x + threadIdx.x;
    if (i < E) atomicAdd(&g_cnt[dst[i]], 1);
}

__global__ __launch_bounds__(1024)
void k_scan(int n) {
    __shared__ int sh[1024];
    __shared__ int carry;
    int tid = threadIdx.x;
    if (tid == 0) carry = 0;
    __syncthreads();
    for (int base = 0; base < n; base += 1024) {
        int i = base + tid;
        int v = (i < n) ? g_cnt[i] : 0;
        sh[tid] = v;
        __syncthreads();
        #pragma unroll
        for (int off = 1; off < 1024; off <<= 1) {
            int t = (tid >= off) ? sh[tid - off] : 0;
            __syncthreads();
            sh[tid] += t;
            __syncthreads();
        }
        if (i < n) g_row[i] = sh[tid] - v + carry;   // exclusive
        int total = sh[1023];
        __syncthreads();
        if (tid == 0) carry += total;
        __syncthreads();
    }
    if (tid == 0) g_row[n] = carry;
}

__global__ void k_scatter(const int* __restrict__ src, const int* __restrict__ dst, int E) {
    int i = blockIdx.x * blockDim.x + threadIdx.x;
    if (i >= E) return;
    int d = dst[i];
    int pos = g_row[d] + atomicAdd(&g_fill[d], 1);
    g_eidx[pos] = src[i];
}

// ---------------- mma helpers ----------------
// pack two floats into bf16x2: first arg -> low half, second -> high half
__device__ __forceinline__ unsigned pkbf2(float lo, float hi) {
    unsigned r; asm("cvt.rn.bf16x2.f32 %0, %1, %2;" : "=r"(r) : "f"(hi), "f"(lo));
    return r;
}
__device__ __forceinline__ float phi_(unsigned u) { return __uint_as_float(u & 0xffff0000u); }
__device__ __forceinline__ float plo_(unsigned u) { return __uint_as_float(u << 16); }
__device__ __forceinline__ void split_store(unsigned* hi, unsigned* lo, float x0, float x1) {
    unsigned h = pkbf2(x0, x1);
    *hi = h;
    *lo = pkbf2(x0 - plo_(h), x1 - phi_(h));
}
__device__ __forceinline__ void mma_bf16(float c[4], unsigned a0, unsigned a1,
                                         unsigned a2, unsigned a3,
                                         unsigned b0, unsigned b1) {
    asm volatile(
        "mma.sync.aligned.m16n8k16.row.col.f32.bf16.bf16.f32 "
        "{%0,%1,%2,%3}, {%4,%5,%6,%7}, {%8,%9}, {%0,%1,%2,%3};"
        : "+f"(c[0]), "+f"(c[1]), "+f"(c[2]), "+f"(c[3])
        : "r"(a0), "r"(a1), "r"(a2), "r"(a3), "r"(b0), "r"(b1));
}

// ================= big input GEMMs: split-bf16, double-buffered pipeline =================
#define APLD 20
#define BPLD 136

struct MmaSmem {
    unsigned Ahi[2][128][APLD];
    unsigned Alo[2][128][APLD];
    unsigned Bhi[2][16][BPLD];
    unsigned Blo[2][16][BPLD];
};
#define MMA_SMEM_BYTES ((int)sizeof(MmaSmem))

__global__ __launch_bounds__(256, 1)
void k_mma_gemm(const float* __restrict__ Ai, const float* __restrict__ At,
                const float* __restrict__ Bi, const float* __restrict__ Bt,
                float* __restrict__ Ci, float* __restrict__ Ct,
                int M, int Ki, int Kt) {
    extern __shared__ char smem_raw[];
    MmaSmem& s = *reinterpret_cast<MmaSmem*>(smem_raw);
    int sel = blockIdx.y;
    const float* A = sel ? At : Ai;
    const float* B = sel ? Bt : Bi;
    float*       C = sel ? Ct : Ci;
    int K = sel ? Kt : Ki;
    int ntile = K >> 5;

    int tid  = threadIdx.x;
    int warp = tid >> 5, lane = tid & 31;
    int wm = warp & 1;
    int wn = warp >> 1;
    int grp = lane >> 2, q = lane & 3;
    int m0 = blockIdx.x * 128;

    int ar[4], ac4[4];
    #pragma unroll
    for (int i = 0; i < 4; ++i) { int f4 = tid + i * 256; ar[i] = f4 >> 3; ac4[i] = f4 & 7; }
    int bkp[8], bc[8];
    #pragma unroll
    for (int i = 0; i < 8; ++i) { int idx = tid + i * 256; bkp[i] = idx >> 7; bc[i] = idx & 127; }

    float4 apf[4];
    float2 bpf[8];

    auto load_tile = [&](int k0) {
        #pragma unroll
        for (int i = 0; i < 4; ++i) {
            apf[i] = make_float4(0.f, 0.f, 0.f, 0.f);
            if (m0 + ar[i] < M)
                apf[i] = *(const float4*)&A[(size_t)(m0 + ar[i]) * K + k0 + ac4[i] * 4];
        }
        #pragma unroll
        for (int i = 0; i < 8; ++i) {
            bpf[i].x = B[(size_t)(k0 + 2 * bkp[i])     * 128 + bc[i]];
            bpf[i].y = B[(size_t)(k0 + 2 * bkp[i] + 1) * 128 + bc[i]];
        }
    };

    auto store_tile = [&](int buf) {
        #pragma unroll
        for (int i = 0; i < 4; ++i) {
            unsigned h0 = pkbf2(apf[i].x, apf[i].y);
            unsigned h1 = pkbf2(apf[i].z, apf[i].w);
            *(uint2*)&s.Ahi[buf][ar[i]][2 * ac4[i]] = make_uint2(h0, h1);
            *(uint2*)&s.Alo[buf][ar[i]][2 * ac4[i]] =
                make_uint2(pkbf2(apf[i].x - plo_(h0), apf[i].y - phi_(h0)),
                           pkbf2(apf[i].z - plo_(h1), apf[i].w - phi_(h1)));
        }
        #pragma unroll
        for (int i = 0; i < 8; ++i) {
            unsigned h = pkbf2(bpf[i].x, bpf[i].y);
            s.Bhi[buf][bkp[i]][bc[i]] = h;
            s.Blo[buf][bkp[i]][bc[i]] = pkbf2(bpf[i].x - plo_(h), bpf[i].y - phi_(h));
        }
    };

    float acc[4][4][4];
    #pragma unroll
    for (int i = 0; i < 4; ++i)
        #pragma unroll
        for (int j = 0; j < 4; ++j)
            #pragma unroll
            for (int k = 0; k < 4; ++k) acc[i][j][k] = 0.f;

    load_tile(0);
    store_tile(0);
    __syncthreads();

    #pragma unroll 1
    for (int t = 0; t < ntile; ++t) {
        int buf = t & 1;
        if (t + 1 < ntile) load_tile((t + 1) * 32);

        #pragma unroll
        for (int sstep = 0; sstep < 2; ++sstep) {
            int p = sstep * 8 + q;
            unsigned af[4][4], bh[4][2], bl[4][2];
            #pragma unroll
            for (int mt = 0; mt < 4; ++mt) {
                int m = wm * 64 + mt * 16 + grp;
                af[mt][0] = s.Ahi[buf][m][p];
                af[mt][1] = s.Ahi[buf][m + 8][p];
                af[mt][2] = s.Ahi[buf][m][p + 4];
                af[mt][3] = s.Ahi[buf][m + 8][p + 4];
            }
            #pragma unroll
            for (int nt = 0; nt < 4; ++nt) {
                int n = wn * 32 + nt * 8 + grp;
                bh[nt][0] = s.Bhi[buf][p][n];      bh[nt][1] = s.Bhi[buf][p + 4][n];
                bl[nt][0] = s.Blo[buf][p][n];      bl[nt][1] = s.Blo[buf][p + 4][n];
            }
            #pragma unroll
            for (int mt = 0; mt < 4; ++mt)
                #pragma unroll
                for (int nt = 0; nt < 4; ++nt) {
                    mma_bf16(acc[mt][nt], af[mt][0], af[mt][1], af[mt][2], af[mt][3],
                             bh[nt][0], bh[nt][1]);
                    mma_bf16(acc[mt][nt], af[mt][0], af[mt][1], af[mt][2], af[mt][3],
                             bl[nt][0], bl[nt][1]);
                }
            #pragma unroll
            for (int mt = 0; mt < 4; ++mt) {
                int m = wm * 64 + mt * 16 + grp;
                af[mt][0] = s.Alo[buf][m][p];
                af[mt][1] = s.Alo[buf][m + 8][p];
                af[mt][2] = s.Alo[buf][m][p + 4];
                af[mt][3] = s.Alo[buf][m + 8][p + 4];
            }
            #pragma unroll
            for (int mt = 0; mt < 4; ++mt)
                #pragma unroll
                for (int nt = 0; nt < 4; ++nt)
                    mma_bf16(acc[mt][nt], af[mt][0], af[mt][1], af[mt][2], af[mt][3],
                             bh[nt][0], bh[nt][1]);
        }

        if (t + 1 < ntile) store_tile((t + 1) & 1);
        __syncthreads();
    }

    #pragma unroll
    for (int mt = 0; mt < 4; ++mt) {
        int m = m0 + wm * 64 + mt * 16 + grp;
        #pragma unroll
        for (int nt = 0; nt < 4; ++nt) {
            int n = wn * 32 + nt * 8 + 2 * q;
            if (m < M)
                *(float2*)&C[(size_t)m * 128 + n] = make_float2(acc[mt][nt][0], acc[mt][nt][1]);
            if (m + 8 < M)
                *(float2*)&C[(size_t)(m + 8) * 128 + n] = make_float2(acc[mt][nt][2], acc[mt][nt][3]);
        }
    }
}

// ================= fused per-node pipeline v3: split-bf16 smem =================
// X tiles stored as packed bf16x2 hi/lo pairs (64 pairs/row, LD 68).
// Fragment LDS bank = 4*grp + q : conflict-free. All MMAs m16n8k16 bf16.
#define XP 68

struct SmemN {
    unsigned Ehi[32][XP], Elo[32][XP];
    unsigned Ahi[32][XP], Alo[32][XP];
    unsigned Bhi[32][XP], Blo[32][XP];
    unsigned Hhi[32][XP], Hlo[32][XP];
    float red[32][8][2];
    float g[32];
};
#define NODE_SMEM_BYTES ((int)sizeof(SmemN))

__device__ __forceinline__ void zacc(float acc[2][2][4]) {
    #pragma unroll
    for (int i = 0; i < 2; ++i)
        #pragma unroll
        for (int j = 0; j < 2; ++j)
            #pragma unroll
            for (int k = 0; k < 4; ++k) acc[i][j][k] = 0.f;
}

// gate passes: hh + lh (A error compensated; W hi only)
__device__ __forceinline__ void npassG(const unsigned (*__restrict__ Xhi)[XP],
                                       const unsigned (*__restrict__ Xlo)[XP],
                                       const float* __restrict__ W,
                                       float acc[2][2][4], int n0, int grp, int q) {
    #pragma unroll
    for (int c = 0; c < 8; ++c) {
        int pb = c * 8, k0 = c * 16;
        unsigned ah[2][4], al[2][4], b[2][2];
        #pragma unroll
        for (int mt = 0; mt < 2; ++mt) {
            int r = mt * 16 + grp;
            ah[mt][0] = Xhi[r][pb + q];     ah[mt][1] = Xhi[r + 8][pb + q];
            ah[mt][2] = Xhi[r][pb + q + 4]; ah[mt][3] = Xhi[r + 8][pb + q + 4];
            al[mt][0] = Xlo[r][pb + q];     al[mt][1] = Xlo[r + 8][pb + q];
            al[mt][2] = Xlo[r][pb + q + 4]; al[mt][3] = Xlo[r + 8][pb + q + 4];
        }
        #pragma unroll
        for (int nt = 0; nt < 2; ++nt) {
            int col = n0 + nt * 8 + grp;
            b[nt][0] = pkbf2(__ldg(&W[(k0 + 2 * q)     * 128 + col]),
                             __ldg(&W[(k0 + 2 * q + 1) * 128 + col]));
            b[nt][1] = pkbf2(__ldg(&W[(k0 + 2 * q + 8) * 128 + col]),
                             __ldg(&W[(k0 + 2 * q + 9) * 128 + col]));
        }
        #pragma unroll
        for (int mt = 0; mt < 2; ++mt)
            #pragma unroll
            for (int nt = 0; nt < 2; ++nt) {
                mma_bf16(acc[mt][nt], ah[mt][0], ah[mt][1], ah[mt][2], ah[mt][3],
                         b[nt][0], b[nt][1]);
                mma_bf16(acc[mt][nt], al[mt][0], al[mt][1], al[mt][2], al[mt][3],
                         b[nt][0], b[nt][1]);
            }
    }
}

// value passes: hh + hl + lh (~2^-16)
__device__ __forceinline__ void npassV(const unsigned (*__restrict__ Xhi)[XP],
                                       const unsigned (*__restrict__ Xlo)[XP],
                                       const float* __restrict__ W,
                                       float acc[2][2][4], int n0, int grp, int q) {
    #pragma unroll
    for (int c = 0; c < 8; ++c) {
        int pb = c * 8, k0 = c * 16;
        unsigned ah[2][4], al[2][4], bh[2][2], bl[2][2];
        #pragma unroll
        for (int mt = 0; mt < 2; ++mt) {
            int r = mt * 16 + grp;
            ah[mt][0] = Xhi[r][pb + q];     ah[mt][1] = Xhi[r + 8][pb + q];
            ah[mt][2] = Xhi[r][pb + q + 4]; ah[mt][3] = Xhi[r + 8][pb + q + 4];
            al[mt][0] = Xlo[r][pb + q];     al[mt][1] = Xlo[r + 8][pb + q];
            al[mt][2] = Xlo[r][pb + q + 4]; al[mt][3] = Xlo[r + 8][pb + q + 4];
        }
        #pragma unroll
        for (int nt = 0; nt < 2; ++nt) {
            int col = n0 + nt * 8 + grp;
            float w0 = __ldg(&W[(k0 + 2 * q)     * 128 + col]);
            float w1 = __ldg(&W[(k0 + 2 * q + 1) * 128 + col]);
            float w2 = __ldg(&W[(k0 + 2 * q + 8) * 128 + col]);
            float w3 = __ldg(&W[(k0 + 2 * q + 9) * 128 + col]);
            unsigned h0 = pkbf2(w0, w1), h1 = pkbf2(w2, w3);
            bh[nt][0] = h0; bh[nt][1] = h1;
            bl[nt][0] = pkbf2(w0 - plo_(h0), w1 - phi_(h0));
            bl[nt][1] = pkbf2(w2 - plo_(h1), w3 - phi_(h1));
        }
        #pragma unroll
        for (int mt = 0; mt < 2; ++mt)
            #pragma unroll
            for (int nt = 0; nt < 2; ++nt) {
                mma_bf16(acc[mt][nt], ah[mt][0], ah[mt][1], ah[mt][2], ah[mt][3],
                         bh[nt][0], bh[nt][1]);
                mma_bf16(acc[mt][nt], ah[mt][0], ah[mt][1], ah[mt][2], ah[mt][3],
                         bl[nt][0], bl[nt][1]);
                mma_bf16(acc[mt][nt], al[mt][0], al[mt][1], al[mt][2], al[mt][3],
                         bh[nt][0], bh[nt][1]);
            }
    }
}

// relu(acc + bias) -> H pairs
__device__ __forceinline__ void relu_store(SmemN& s, float acc[2][2][4],
                                           const float* __restrict__ bp,
                                           int n0, int grp, int q) {
    #pragma unroll
    for (int nt = 0; nt < 2; ++nt) {
        int colp = (n0 >> 1) + nt * 4 + q;   // pair column
        float2 b = __ldg((const float2*)&bp[2 * colp]);
        #pragma unroll
        for (int mt = 0; mt < 2; ++mt) {
            int r1 = mt * 16 + grp;
            split_store(&s.Hhi[r1][colp], &s.Hlo[r1][colp],
                        fmaxf(acc[mt][nt][0] + b.x, 0.f), fmaxf(acc[mt][nt][1] + b.y, 0.f));
            split_store(&s.Hhi[r1 + 8][colp], &s.Hlo[r1 + 8][colp],
                        fmaxf(acc[mt][nt][2] + b.x, 0.f), fmaxf(acc[mt][nt][3] + b.y, 0.f));
        }
    }
}

__device__ __forceinline__ void gate_finish(SmemN& s, float acc[2][2][4],
                                            const float* __restrict__ b2p,
                                            const float* __restrict__ w3p,
                                            const float* __restrict__ b3p,
                                            int n0, int grp, int q, int warp, int tid) {
    float part[4] = {0.f, 0.f, 0.f, 0.f};
    #pragma unroll
    for (int nt = 0; nt < 2; ++nt) {
        int col = n0 + nt * 8 + 2 * q;
        float2 b2 = __ldg((const float2*)&b2p[col]);
        float2 w3 = __ldg((const float2*)&w3p[col]);
        #pragma unroll
        for (int mt = 0; mt < 2; ++mt) {
            part[mt * 2 + 0] += fmaxf(acc[mt][nt][0] + b2.x, 0.f) * w3.x
                              + fmaxf(acc[mt][nt][1] + b2.y, 0.f) * w3.y;
            part[mt * 2 + 1] += fmaxf(acc[mt][nt][2] + b2.x, 0.f) * w3.x
                              + fmaxf(acc[mt][nt][3] + b2.y, 0.f) * w3.y;
        }
    }
    #pragma unroll
    for (int i = 0; i < 4; ++i) {
        part[i] += __shfl_xor_sync(0xffffffffu, part[i], 1);
        part[i] += __shfl_xor_sync(0xffffffffu, part[i], 2);
    }
    if (q == 0) {
        #pragma unroll
        for (int mt = 0; mt < 2; ++mt) {
            s.red[mt * 16 + grp][warp][0]     = part[mt * 2 + 0];
            s.red[mt * 16 + grp + 8][warp][0] = part[mt * 2 + 1];
        }
    }
    __syncthreads();
    if (tid < 32) {
        float v = 0.f;
        #pragma unroll
        for (int w = 0; w < 8; ++w) v += s.red[tid][w][0];
        s.g[tid] = 1.f / (1.f + expf(-(v + __ldg(b3p))));
    }
    __syncthreads();
}

// gated mix of pair arrays: X = g*X + (1-g)*E   (rows r8*4..+3, pairs 2*c32..+1)
__device__ __forceinline__ void mix_pairs(unsigned (*__restrict__ Xhi)[XP],
                                          unsigned (*__restrict__ Xlo)[XP],
                                          const unsigned (*__restrict__ Ehi)[XP],
                                          const unsigned (*__restrict__ Elo)[XP],
                                          const float* __restrict__ gv_, int r8, int c32) {
    #pragma unroll
    for (int i = 0; i < 4; ++i) {
        int r = r8 * 4 + i;
        float gv = gv_[r];
        #pragma unroll
        for (int pp = 0; pp < 2; ++pp) {
            int p = 2 * c32 + pp;
            unsigned xh = Xhi[r][p], xl = Xlo[r][p];
            unsigned eh = Ehi[r][p], el = Elo[r][p];
            float x0 = plo_(xh) + plo_(xl), x1 = phi_(xh) + phi_(xl);
            float e0 = plo_(eh) + plo_(el), e1 = phi_(eh) + phi_(el);
            split_store(&Xhi[r][p], &Xlo[r][p],
                        gv * x0 + (1.f - gv) * e0, gv * x1 + (1.f - gv) * e1);
        }
    }
}

__global__ __launch_bounds__(256, 3)
void k_node(const int* __restrict__ node_id, const float* __restrict__ emb,
            const float* __restrict__ iW1, const float* __restrict__ ib1,
            const float* __restrict__ iW2, const float* __restrict__ ib2,
            const float* __restrict__ iW3, const float* __restrict__ ib3,
            const float* __restrict__ tW1, const float* __restrict__ tb1,
            const float* __restrict__ tW2, const float* __restrict__ tb2,
            const float* __restrict__ tW3, const float* __restrict__ tb3,
            const float* __restrict__ cW,  const float* __restrict__ cb,
            const float* __restrict__ fW,  const float* __restrict__ attn_a,
            int N) {
    extern __shared__ char smem_raw[];
    SmemN& s = *reinterpret_cast<SmemN*>(smem_raw);
    int tid = threadIdx.x;
    int warp = tid >> 5, lane = tid & 31;
    int grp = lane >> 2, q = lane & 3;
    int n0 = warp * 16;
    int r8 = tid >> 5, c32 = tid & 31;
    int base = blockIdx.x * 32;

    // ---- gather + split-store E, A(img), B(txt) ----
    #pragma unroll
    for (int it = 0; it < 4; ++it) {
        int idx = tid + it * 256;
        int n = idx >> 5, c4 = idx & 31;
        int gn = base + n;
        int nid = (gn < N) ? __ldg(&node_id[gn]) : 0;
        float4 ev = *(const float4*)&emb[(size_t)nid * 128 + c4 * 4];
        split_store(&s.Ehi[n][2 * c4],     &s.Elo[n][2 * c4],     ev.x, ev.y);
        split_store(&s.Ehi[n][2 * c4 + 1], &s.Elo[n][2 * c4 + 1], ev.z, ev.w);
        float4 iv = make_float4(0.f, 0.f, 0.f, 0.f);
        float4 tv = make_float4(0.f, 0.f, 0.f, 0.f);
        if (gn < N) {
            iv = *(const float4*)&g_img_f[(size_t)gn * 128 + c4 * 4];
            tv = *(const float4*)&g_txt_f[(size_t)gn * 128 + c4 * 4];
        }
        split_store(&s.Ahi[n][2 * c4],     &s.Alo[n][2 * c4],     iv.x, iv.y);
        split_store(&s.Ahi[n][2 * c4 + 1], &s.Alo[n][2 * c4 + 1], iv.z, iv.w);
        split_store(&s.Bhi[n][2 * c4],     &s.Blo[n][2 * c4],     tv.x, tv.y);
        split_store(&s.Bhi[n][2 * c4 + 1], &s.Blo[n][2 * c4 + 1], tv.z, tv.w);
    }
    __syncthreads();

    float acc[2][2][4];

    // ==== img gate MLP ====
    zacc(acc);
    npassG(s.Ehi, s.Elo, iW1,             acc, n0, grp, q);
    npassG(s.Ahi, s.Alo, iW1 + 128 * 128, acc, n0, grp, q);
    relu_store(s, acc, ib1, n0, grp, q);
    __syncthreads();

    zacc(acc);
    npassG(s.Hhi, s.Hlo, iW2, acc, n0, grp, q);
    gate_finish(s, acc, ib2, iW3, ib3, n0, grp, q, warp, tid);

    mix_pairs(s.Ahi, s.Alo, s.Ehi, s.Elo, s.g, r8, c32);

    // ==== txt gate MLP ====
    zacc(acc);
    npassG(s.Ehi, s.Elo, tW1,             acc, n0, grp, q);
    npassG(s.Bhi, s.Blo, tW1 + 128 * 128, acc, n0, grp, q);
    relu_store(s, acc, tb1, n0, grp, q);
    __syncthreads();

    zacc(acc);
    npassG(s.Hhi, s.Hlo, tW2, acc, n0, grp, q);
    gate_finish(s, acc, tb2, tW3, tb3, n0, grp, q, warp, tid);

    mix_pairs(s.Bhi, s.Blo, s.Ehi, s.Elo, s.g, r8, c32);
    __syncthreads();   // A,B final before comb reads them

    // ==== comb gate (linear) + h ====
    zacc(acc);
    npassV(s.Ahi, s.Alo, cW,             acc, n0, grp, q);
    npassV(s.Bhi, s.Blo, cW + 128 * 128, acc, n0, grp, q);
    {
        #pragma unroll
        for (int nt = 0; nt < 2; ++nt) {
            int colp = (n0 >> 1) + nt * 4 + q;
            float2 cbv = __ldg((const float2*)&cb[2 * colp]);
            #pragma unroll
            for (int mt = 0; mt < 2; ++mt) {
                int r1 = mt * 16 + grp, r2 = r1 + 8;
                float g0 = acc[mt][nt][0] + cbv.x;
                float g1 = acc[mt][nt][1] + cbv.y;
                float g2 = acc[mt][nt][2] + cbv.x;
                float g3 = acc[mt][nt][3] + cbv.y;
                unsigned a1h = s.Ahi[r1][colp], a1l = s.Alo[r1][colp];
                unsigned b1h = s.Bhi[r1][colp], b1l = s.Blo[r1][colp];
                unsigned a2h = s.Ahi[r2][colp], a2l = s.Alo[r2][colp];
                unsigned b2h = s.Bhi[r2][colp], b2l = s.Blo[r2][colp];
                float av0 = plo_(a1h) + plo_(a1l), av1 = phi_(a1h) + phi_(a1l);
                float bv0 = plo_(b1h) + plo_(b1l), bv1 = phi_(b1h) + phi_(b1l);
                float aw0 = plo_(a2h) + plo_(a2l), aw1 = phi_(a2h) + phi_(a2l);
                float bw0 = plo_(b2h) + plo_(b2l), bw1 = phi_(b2h) + phi_(b2l);
                split_store(&s.Hhi[r1][colp], &s.Hlo[r1][colp],
                            g0 * av0 + (1.f - g0) * bv0, g1 * av1 + (1.f - g1) * bv1);
                split_store(&s.Hhi[r2][colp], &s.Hlo[r2][colp],
                            g2 * aw0 + (1.f - g2) * bw0, g3 * aw1 + (1.f - g3) * bw1);
            }
        }
    }
    __syncthreads();

    // ==== z = h @ fc_W ; z store + attention logits ====
    zacc(acc);
    npassV(s.Hhi, s.Hlo, fW, acc, n0, grp, q);
    {
        float p1[4] = {0.f, 0.f, 0.f, 0.f};
        float p2[4] = {0.f, 0.f, 0.f, 0.f};
        #pragma unroll
        for (int nt = 0; nt < 2; ++nt) {
            int col = n0 + nt * 8 + 2 * q;
            float2 a1 = __ldg((const float2*)&attn_a[col]);
            float2 a2 = __ldg((const float2*)&attn_a[128 + col]);
            #pragma unroll
            for (int mt = 0; mt < 2; ++mt) {
                int r1 = mt * 16 + grp, r2 = r1 + 8;
                int g1_ = base + r1, g2_ = base + r2;
                if (g1_ < N)
                    *(float2*)&g_z[(size_t)g1_ * 128 + col] =
                        make_float2(acc[mt][nt][0], acc[mt][nt][1]);
                if (g2_ < N)
                    *(float2*)&g_z[(size_t)g2_ * 128 + col] =
                        make_float2(acc[mt][nt][2], acc[mt][nt][3]);
                p1[mt * 2 + 0] += acc[mt][nt][0] * a1.x + acc[mt][nt][1] * a1.y;
                p1[mt * 2 + 1] += acc[mt][nt][2] * a1.x + acc[mt][nt][3] * a1.y;
                p2[mt * 2 + 0] += acc[mt][nt][0] * a2.x + acc[mt][nt][1] * a2.y;
                p2[mt * 2 + 1] += acc[mt][nt][2] * a2.x + acc[mt][nt][3] * a2.y;
            }
        }
        #pragma unroll
        for (int i = 0; i < 4; ++i) {
            p1[i] += __shfl_xor_sync(0xffffffffu, p1[i], 1);
            p1[i] += __shfl_xor_sync(0xffffffffu, p1[i], 2);
            p2[i] += __shfl_xor_sync(0xffffffffu, p2[i], 1);
            p2[i] += __shfl_xor_sync(0xffffffffu, p2[i], 2);
        }
        if (q == 0) {
            #pragma unroll
            for (int mt = 0; mt < 2; ++mt) {
                s.red[mt * 16 + grp][warp][0]     = p1[mt * 2 + 0];
                s.red[mt * 16 + grp + 8][warp][0] = p1[mt * 2 + 1];
                s.red[mt * 16 + grp][warp][1]     = p2[mt * 2 + 0];
                s.red[mt * 16 + grp + 8][warp][1] = p2[mt * 2 + 1];
            }
        }
        __syncthreads();
        if (tid < 32) {
            float v1 = 0.f, v2 = 0.f;
            #pragma unroll
            for (int w = 0; w < 8; ++w) { v1 += s.red[tid][w][0]; v2 += s.red[tid][w][1]; }
            int gn = base + tid;
            if (gn < N) { g_esrc[gn] = v1; g_edst[gn] = v2; }
        }
    }
}

// ---------------- CSR aggregate: warp per dst node, no atomics ----------------
__global__ __launch_bounds__(256)
void k_agg(float* __restrict__ out, int N) {
    int w = (int)((blockIdx.x * (size_t)blockDim.x + threadIdx.x) >> 5);
    int lane = threadIdx.x & 31;
    if (w >= N) return;
    int beg = g_row[w], end = g_row[w + 1];
    float ed = g_edst[w];

    float m = -CUDART_INF_F;
    for (int i = beg + lane; i < end; i += 32) {
        float e = g_esrc[g_eidx[i]] + ed;
        e = (e >= 0.f) ? e : 0.01f * e;
        m = fmaxf(m, e);
    }
    #pragma unroll
    for (int off = 16; off > 0; off >>= 1)
        m = fmaxf(m, __shfl_xor_sync(0xffffffffu, m, off));

    float4 acc = make_float4(0.f, 0.f, 0.f, 0.f);
    float denom = 0.f;
    for (int basei = beg; basei < end; basei += 32) {
        int idx = basei + lane;
        float wgt = 0.f; int sj = 0;
        if (idx < end) {
            sj = g_eidx[idx];
            float e = g_esrc[sj] + ed;
            e = (e >= 0.f) ? e : 0.01f * e;
            wgt = expf(e - m);
        }
        int cnt = min(32, end - basei);
        for (int j = 0; j < cnt; ++j) {
            float wj = __shfl_sync(0xffffffffu, wgt, j);
            int   s_ = __shfl_sync(0xffffffffu, sj, j);
            float4 zv = __ldg((const float4*)&g_z[(size_t)s_ * 128 + lane * 4]);
            acc.x = fmaf(wj, zv.x, acc.x);
            acc.y = fmaf(wj, zv.y, acc.y);
            acc.z = fmaf(wj, zv.z, acc.z);
            acc.w = fmaf(wj, zv.w, acc.w);
            denom += wj;
        }
    }
    float inv = (denom > 1e-20f) ? 1.f / denom : 0.f;
    acc.x *= inv; acc.y *= inv; acc.z *= inv; acc.w *= inv;
    *(float4*)&out[(size_t)w * 128 + lane * 4] = acc;
}

// ---------------- launch ----------------
extern "C" void kernel_launch(void* const* d_in, const int* in_sizes, int n_in,
                              void* d_out, int out_size) {
    const int*   node_id = (const int*)  d_in[0];
    const float* img_h   = (const float*)d_in[1];
    const float* txt_h   = (const float*)d_in[2];
    const int*   src     = (const int*)  d_in[3];
    const int*   dst     = (const int*)  d_in[4];
    const float* emb     = (const float*)d_in[5];
    const float* W_img   = (const float*)d_in[6];
    const float* iW1     = (const float*)d_in[7];
    const float* ib1     = (const float*)d_in[8];
    const float* iW2     = (const float*)d_in[9];
    const float* ib2     = (const float*)d_in[10];
    const float* iW3     = (const float*)d_in[11];
    const float* ib3     = (const float*)d_in[12];
    const float* W_txt   = (const float*)d_in[13];
    const float* tW1     = (const float*)d_in[14];
    const float* tb1     = (const float*)d_in[15];
    const float* tW2     = (const float*)d_in[16];
    const float* tb2     = (const float*)d_in[17];
    const float* tW3     = (const float*)d_in[18];
    const float* tb3     = (const float*)d_in[19];
    const float* cW      = (const float*)d_in[20];
    const float* cb      = (const float*)d_in[21];
    const float* fW      = (const float*)d_in[22];
    const float* attn_a  = (const float*)d_in[23];

    int N = in_sizes[0];
    int E = in_sizes[3];
    int IMG_D = in_sizes[1] / N;
    int TXT_D = in_sizes[2] / N;
    float* out = (float*)d_out;

    float *p_img_f, *p_txt_f;
    cudaGetSymbolAddress((void**)&p_img_f, g_img_f);
    cudaGetSymbolAddress((void**)&p_txt_f, g_txt_f);

    cudaFuncSetAttribute(k_node, cudaFuncAttributeMaxDynamicSharedMemorySize, NODE_SMEM_BYTES);
    cudaFuncSetAttribute(k_mma_gemm, cudaFuncAttributeMaxDynamicSharedMemorySize, MMA_SMEM_BYTES);

    // launch order puts k_mma_gemm at index 3 (ncu captures index 3)
    k_zero<<<(N + 255) / 256, 256>>>(N);                        // 0
    k_count<<<(E + 255) / 256, 256>>>(dst, E);                  // 1
    k_scan<<<1, 1024>>>(N);                                     // 2
    dim3 ggrid((N + 127) / 128, 2);
    k_mma_gemm<<<ggrid, 256, MMA_SMEM_BYTES>>>(img_h, txt_h, W_img, W_txt,
                                               p_img_f, p_txt_f, N, IMG_D, TXT_D); // 3
    k_scatter<<<(E + 255) / 256, 256>>>(src, dst, E);           // 4
    k_node<<<(N + 31) / 32, 256, NODE_SMEM_BYTES>>>(            // 5
        node_id, emb,
        iW1, ib1, iW2, ib2, iW3, ib3,
        tW1, tb1, tW2, tb2, tW3, tb3,
        cW, cb, fW, attn_a, N);
    k_agg<<<(N * 32 + 255) / 256, 256>>>(out, N);               // 6
}